// round 1
// baseline (speedup 1.0000x reference)
#include <cuda_runtime.h>
#include <math.h>

// FourierAttention, FFT-free reformulation.
// B=4, L=8192, H=16, D=64, Ls=64, M=128.
//
// scores[b,h,m,n] = (1/8) * sum_{l,d} q[b,m,l,h,d] * ktilde[b,n,l,h,d]
//   ktilde_re[d] = 0.5*k[d] + (1/64)*sum_{d' same parity} k[d']
//   ktilde_im[d] = sum_{d' opposite parity} (-cot(pi*(d-d')/64)/64) * k[d']
// A = softmax_n(|scores|/64)  -> softmax arg = |S|/512, S = raw GEMM result
// out[b,m,l,h,d] = sum_n A[b,h,m,n] * v[b,n,l,h,d]   (irfft linearity)

#define BDIM 4
#define LDIM 8192
#define HDIM 16
#define DDIM 64
#define LSEG 64
#define MSEG 128
#define BH   (BDIM*HDIM)        // 64
#define KDIM (LSEG*DDIM)        // 4096 contraction length
#define JDIM 256                // 128 re cols | 128 im cols
#define KCH  8                  // kappa split for occupancy
#define ROWSTRIDE 1024          // H*D floats per L-row
#define SEGSTRIDE 65536         // Ls*H*D floats per segment index (m or n)

// Scratch (device globals: allocation-free, graph-capture safe)
__device__ float g_Kt[(size_t)BH * KDIM * JDIM];          // 268 MB
__device__ float g_Cpart[(size_t)KCH * BH * MSEG * JDIM]; // 67 MB
__device__ float g_A[(size_t)BH * MSEG * MSEG];           // 4 MB

// ---------------------------------------------------------------------------
// Kernel 1: build Kt[bh][kappa=(l*64+d)][j]  (j<128: re, j>=128: im)
// grid: 4096 = bh*64 + l, block: 256
// ---------------------------------------------------------------------------
__global__ __launch_bounds__(256) void build_kt(const float* __restrict__ k) {
    __shared__ __align__(16) float ks[64][129];   // [d][n], padded
    __shared__ float keo[2][128];                 // parity sums per n
    __shared__ float ct[128];                     // cot table, idx = delta+64

    int bx = blockIdx.x;
    int l  = bx & 63;
    int bh = bx >> 6;
    int b  = bh >> 4, h = bh & 15;
    int tid = threadIdx.x;

    const float* kbase = k + (size_t)b * (LDIM * ROWSTRIDE) + (size_t)l * ROWSTRIDE + h * DDIM;

    // load k tile [n=128][d=64], transpose into ks[d][n]
#pragma unroll
    for (int i = 0; i < 8; i++) {
        int idx = tid + i * 256;          // 0..2047
        int n   = idx >> 4;
        int dq  = idx & 15;
        float4 v = *(const float4*)(kbase + (size_t)n * SEGSTRIDE + dq * 4);
        ks[dq * 4 + 0][n] = v.x;
        ks[dq * 4 + 1][n] = v.y;
        ks[dq * 4 + 2][n] = v.z;
        ks[dq * 4 + 3][n] = v.w;
    }
    // cot table: ct[delta+64] = -cot(pi*delta/64)/64 for odd delta, else 0
    if (tid < 128) {
        int delta = tid - 64;
        float val = 0.0f;
        if (delta & 1) {
            float x = (float)delta * (1.0f / 64.0f);
            val = -(cospif(x) / sinpif(x)) * (1.0f / 64.0f);
        }
        ct[tid] = val;
    }
    __syncthreads();

    // parity sums: keo[0][n] = sum over even d, keo[1][n] = sum over odd d
    {
        int n = tid & 127;
        int par = tid >> 7;
        float s = 0.0f;
#pragma unroll
        for (int t = 0; t < 32; t++) s += ks[2 * t + par][n];
        keo[par][n] = s;
    }
    __syncthreads();

    float* out = g_Kt + ((size_t)bh * KDIM + (size_t)l * 64) * JDIM;

    if (tid < 128) {
        int n = tid;
#pragma unroll
        for (int d = 0; d < 64; d++) {
            float re = 0.5f * ks[d][n] + (1.0f / 64.0f) * keo[d & 1][n];
            out[(size_t)d * JDIM + n] = re;
        }
    } else {
        int n = tid - 128;
#pragma unroll 4
        for (int d = 0; d < 64; d++) {
            int p = (d + 1) & 1;   // opposite parity start
            float acc = 0.0f;
#pragma unroll
            for (int t = 0; t < 32; t++) {
                int dp = p + 2 * t;
                acc += ct[d - dp + 64] * ks[dp][n];
            }
            out[(size_t)d * JDIM + 128 + n] = acc;
        }
    }
}

// ---------------------------------------------------------------------------
// Kernel 2: scores GEMM partials.
// C[bh][m][j] = sum_kappa Q[bh][m][kappa] * Kt[bh][kappa][j]
// grid (KCH=8, jhalf=2, bh=64), block 256, thread tile 8x8, ktile 16
// ---------------------------------------------------------------------------
__global__ __launch_bounds__(256) void gemm_scores(const float* __restrict__ q) {
    __shared__ __align__(16) float Qs[16][132];   // [kk][m] transposed, padded
    __shared__ __align__(16) float Kts[16][128];  // [kk][j]

    int kc = blockIdx.x;   // kappa chunk 0..7 (512 each)
    int jh = blockIdx.y;   // 0..1
    int bh = blockIdx.z;   // 0..63
    int b  = bh >> 4, h = bh & 15;
    int tid = threadIdx.x;
    int tr = tid >> 4, tc = tid & 15;

    float c[8][8];
#pragma unroll
    for (int i = 0; i < 8; i++)
#pragma unroll
        for (int j = 0; j < 8; j++) c[i][j] = 0.0f;

    const float* qbase  = q + (size_t)b * (LDIM * ROWSTRIDE) + h * DDIM;
    const float* ktbase = g_Kt + (size_t)bh * KDIM * JDIM + (size_t)jh * 128;
    int k0 = kc * 512;

    for (int kt = 0; kt < 32; kt++) {
        int kap = k0 + kt * 16;
        int l   = kap >> 6;
        int dst = kap & 63;

        // load Q tile: 128 m x 16 kappa, transposed into Qs[kk][m]
#pragma unroll
        for (int i = 0; i < 2; i++) {
            int idx = tid + i * 256;       // 0..511
            int m   = idx >> 2;
            int q4  = idx & 3;
            float4 v = *(const float4*)(qbase + (size_t)(m * LSEG + l) * ROWSTRIDE + dst + q4 * 4);
            Qs[q4 * 4 + 0][m] = v.x;
            Qs[q4 * 4 + 1][m] = v.y;
            Qs[q4 * 4 + 2][m] = v.z;
            Qs[q4 * 4 + 3][m] = v.w;
        }
        // load Kt tile: 16 kappa x 128 j (direct)
#pragma unroll
        for (int i = 0; i < 2; i++) {
            int idx = tid + i * 256;
            int kk  = idx >> 5;
            int jq  = idx & 31;
            float4 v = *(const float4*)(ktbase + (size_t)(kap + kk) * JDIM + jq * 4);
            *(float4*)&Kts[kk][jq * 4] = v;
        }
        __syncthreads();

#pragma unroll
        for (int kk = 0; kk < 16; kk++) {
            float a[8], bb[8];
            *(float4*)&a[0]  = *(const float4*)&Qs[kk][tr * 8];
            *(float4*)&a[4]  = *(const float4*)&Qs[kk][tr * 8 + 4];
            *(float4*)&bb[0] = *(const float4*)&Kts[kk][tc * 8];
            *(float4*)&bb[4] = *(const float4*)&Kts[kk][tc * 8 + 4];
#pragma unroll
            for (int i = 0; i < 8; i++)
#pragma unroll
                for (int j = 0; j < 8; j++) c[i][j] += a[i] * bb[j];
        }
        __syncthreads();
    }

    float* cp = g_Cpart + ((size_t)kc * BH + bh) * (MSEG * JDIM) + (size_t)jh * 128;
#pragma unroll
    for (int i = 0; i < 8; i++) {
        int m = tr * 8 + i;
        float4 w0 = make_float4(c[i][0], c[i][1], c[i][2], c[i][3]);
        float4 w1 = make_float4(c[i][4], c[i][5], c[i][6], c[i][7]);
        *(float4*)(cp + (size_t)m * JDIM + tc * 8)     = w0;
        *(float4*)(cp + (size_t)m * JDIM + tc * 8 + 4) = w1;
    }
}

// ---------------------------------------------------------------------------
// Kernel 3: reduce partials, |S|/512, row softmax -> g_A
// grid 64 (bh), block 256 (8 warps x 16 rows each)
// ---------------------------------------------------------------------------
__global__ __launch_bounds__(256) void softmax_k() {
    int bh  = blockIdx.x;
    int tid = threadIdx.x;
    int warp = tid >> 5, lane = tid & 31;

    for (int m = warp; m < MSEG; m += 8) {
        float t[4];
#pragma unroll
        for (int u = 0; u < 4; u++) {
            int n = lane + u * 32;
            float sre = 0.0f, sim = 0.0f;
#pragma unroll
            for (int p = 0; p < KCH; p++) {
                const float* cp = g_Cpart + (((size_t)p * BH + bh) * MSEG + m) * JDIM;
                sre += cp[n];
                sim += cp[n + 128];
            }
            t[u] = sqrtf(sre * sre + sim * sim) * (1.0f / 512.0f);
        }
        float mx = fmaxf(fmaxf(t[0], t[1]), fmaxf(t[2], t[3]));
#pragma unroll
        for (int o = 16; o; o >>= 1) mx = fmaxf(mx, __shfl_xor_sync(0xffffffffu, mx, o));
        float e[4], s = 0.0f;
#pragma unroll
        for (int u = 0; u < 4; u++) { e[u] = expf(t[u] - mx); s += e[u]; }
#pragma unroll
        for (int o = 16; o; o >>= 1) s += __shfl_xor_sync(0xffffffffu, s, o);
        float inv = 1.0f / s;
        float* arow = g_A + ((size_t)bh * MSEG + m) * MSEG;
#pragma unroll
        for (int u = 0; u < 4; u++) arow[lane + u * 32] = e[u] * inv;
    }
}

// ---------------------------------------------------------------------------
// Kernel 4: out[m][l][d] = sum_n A[m][n] * v[n][l][d]
// grid 4096 = bh*64 + l, block 256, thread tile 8m x 4d, n chunked by 32
// ---------------------------------------------------------------------------
__global__ __launch_bounds__(256) void v_gemm(const float* __restrict__ v,
                                              float* __restrict__ out) {
    __shared__ __align__(16) float Ast[32][132];  // [n][m] transposed, padded
    __shared__ __align__(16) float vs[32][68];    // [n][d], padded

    int bx = blockIdx.x;
    int l  = bx & 63;
    int bh = bx >> 6;
    int b  = bh >> 4, h = bh & 15;
    int tid = threadIdx.x;
    int tr = tid >> 4, tc = tid & 15;

    float c[8][4];
#pragma unroll
    for (int i = 0; i < 8; i++)
#pragma unroll
        for (int j = 0; j < 4; j++) c[i][j] = 0.0f;

    const float* vbase = v + (size_t)b * (LDIM * ROWSTRIDE) + (size_t)l * ROWSTRIDE + h * DDIM;
    const float* Abase = g_A + (size_t)bh * MSEG * MSEG;

    for (int nc = 0; nc < 4; nc++) {
        // load A chunk [m=128][n in nc*32..+32), transpose into Ast[n][m]
#pragma unroll
        for (int i = 0; i < 4; i++) {
            int idx = tid + i * 256;       // 0..1023
            int m   = idx >> 3;
            int nq  = idx & 7;
            float4 av = *(const float4*)(Abase + (size_t)m * MSEG + nc * 32 + nq * 4);
            Ast[nq * 4 + 0][m] = av.x;
            Ast[nq * 4 + 1][m] = av.y;
            Ast[nq * 4 + 2][m] = av.z;
            Ast[nq * 4 + 3][m] = av.w;
        }
        // load v chunk [n 32][d 64]
#pragma unroll
        for (int i = 0; i < 2; i++) {
            int idx = tid + i * 256;       // 0..511
            int n   = idx >> 4;
            int dq  = idx & 15;
            float4 vv = *(const float4*)(vbase + (size_t)(nc * 32 + n) * SEGSTRIDE + dq * 4);
            *(float4*)&vs[n][dq * 4] = vv;
        }
        __syncthreads();

#pragma unroll
        for (int nn = 0; nn < 32; nn++) {
            float a[8], bb[4];
            *(float4*)&a[0]  = *(const float4*)&Ast[nn][tr * 8];
            *(float4*)&a[4]  = *(const float4*)&Ast[nn][tr * 8 + 4];
            *(float4*)&bb[0] = *(const float4*)&vs[nn][tc * 4];
#pragma unroll
            for (int i = 0; i < 8; i++)
#pragma unroll
                for (int j = 0; j < 4; j++) c[i][j] += a[i] * bb[j];
        }
        __syncthreads();
    }

    float* obase = out + (size_t)b * (LDIM * ROWSTRIDE) + (size_t)l * ROWSTRIDE + h * DDIM;
#pragma unroll
    for (int i = 0; i < 8; i++) {
        int m = tr * 8 + i;
        float4 w = make_float4(c[i][0], c[i][1], c[i][2], c[i][3]);
        *(float4*)(obase + (size_t)m * SEGSTRIDE + tc * 4) = w;
    }
}

// ---------------------------------------------------------------------------
extern "C" void kernel_launch(void* const* d_in, const int* in_sizes, int n_in,
                              void* d_out, int out_size) {
    const float* q = (const float*)d_in[0];
    const float* k = (const float*)d_in[1];
    const float* v = (const float*)d_in[2];
    // d_in[3] = attn_mask (always 0) — unused
    float* out = (float*)d_out;

    build_kt<<<BH * LSEG, 256>>>(k);
    gemm_scores<<<dim3(KCH, 2, BH), 256>>>(q);
    softmax_k<<<BH, 256>>>();
    v_gemm<<<BH * LSEG, 256>>>(v, out);
}

// round 2
// speedup vs baseline: 1.0832x; 1.0832x over previous
#include <cuda_runtime.h>
#include <math.h>

// FourierAttention, FFT-free reformulation (R2).
// B=4, L=8192, H=16, D=64, Ls=64, M=128.
//
// scores_re folded on the fly:  ktilde_re = 0.5*k + (1/64)*parity_sum(k)
// scores_im via materialized Kt_im (32-tap cot correlation, register-resident taps)
// A = softmax_n(|S|/512); out = A @ v (irfft linearity).
// Both GEMMs use packed fma.rn.f32x2 (2 fp32 FMAs per instruction).

#define BDIM 4
#define LDIM 8192
#define HDIM 16
#define DDIM 64
#define LSEG 64
#define MSEG 128
#define BH   64
#define KDIM 4096
#define KCH  4
#define ROWSTRIDE 1024
#define SEGSTRIDE 65536

typedef unsigned long long ull;

// Scratch (device globals: allocation-free, graph-capture safe)
__device__ float g_Kt[(size_t)BH * KDIM * 128];          // im-transformed K, 134 MB
__device__ float g_KEO[(size_t)BH * LSEG * MSEG * 2];    // parity sums of K, 4 MB
__device__ float g_Cpart[(size_t)KCH * BH * MSEG * 256]; // 33.5 MB
__device__ float g_A[(size_t)BH * MSEG * MSEG];          // 4 MB

__device__ __forceinline__ ull pack2(float x, float y) {
    ull r; asm("mov.b64 %0,{%1,%2};" : "=l"(r) : "f"(x), "f"(y)); return r;
}
__device__ __forceinline__ void ffma2(ull& c, ull a, ull b) {
    asm("fma.rn.f32x2 %0,%1,%2,%0;" : "+l"(c) : "l"(a), "l"(b));
}
__device__ __forceinline__ float2 unpack2(ull c) {
    float2 r; asm("mov.b64 {%0,%1},%2;" : "=f"(r.x), "=f"(r.y) : "l"(c)); return r;
}

// ---------------------------------------------------------------------------
// Kernel 1: Kt_im[bh][l*64+d][n] + parity sums KEO[bh][l][n][par]
// grid 4096 = bh*64 + l, block 256. Taps in registers -> FMA-bound.
// ---------------------------------------------------------------------------
__global__ __launch_bounds__(256) void build_ktim(const float* __restrict__ k) {
    __shared__ __align__(16) float ks[64][129];  // [d][n]
    __shared__ float ct[128];                    // cot table, idx = delta+64

    int bx = blockIdx.x;
    int l  = bx & 63;
    int bh = bx >> 6;
    int b  = bh >> 4, h = bh & 15;
    int tid = threadIdx.x;

    const float* kbase = k + (size_t)b * (LDIM * ROWSTRIDE) + (size_t)l * ROWSTRIDE + h * DDIM;

#pragma unroll
    for (int i = 0; i < 8; i++) {
        int idx = tid + i * 256;
        int n = idx >> 4, dq = idx & 15;
        float4 v = *(const float4*)(kbase + (size_t)n * SEGSTRIDE + dq * 4);
        ks[dq * 4 + 0][n] = v.x;
        ks[dq * 4 + 1][n] = v.y;
        ks[dq * 4 + 2][n] = v.z;
        ks[dq * 4 + 3][n] = v.w;
    }
    if (tid < 128) {
        int delta = tid - 64;
        float val = 0.0f;
        if (delta & 1) {
            float x = (float)delta * (1.0f / 64.0f);
            val = -(cospif(x) / sinpif(x)) * (1.0f / 64.0f);
        }
        ct[tid] = val;
    }
    __syncthreads();

    int n = tid & 127;
    int qp = tid >> 7;  // output-d parity handled by this thread

    // parity sum (parity qp) -> KEO
    {
        float s = 0.0f;
#pragma unroll
        for (int t = 0; t < 32; t++) s += ks[2 * t + qp][n];
        g_KEO[(((size_t)bh * 64 + l) * 128 + n) * 2 + qp] = s;
    }

    // im correlation: d = qp + 2*dd, dp = (1-qp) + 2*t, delta = 2*(dd-t) + 2*qp - 1
    float ctr[63];
#pragma unroll
    for (int u = 0; u < 63; u++) ctr[u] = ct[2 * u + 2 * qp + 1];  // = ct[2(u-31)+2qp-1+64]
    float acc[32];
#pragma unroll
    for (int dd = 0; dd < 32; dd++) acc[dd] = 0.0f;
#pragma unroll
    for (int t = 0; t < 32; t++) {
        float kv = ks[(1 - qp) + 2 * t][n];
#pragma unroll
        for (int dd = 0; dd < 32; dd++) acc[dd] += ctr[dd - t + 31] * kv;
    }
    float* out = g_Kt + ((size_t)bh * KDIM + (size_t)l * 64) * 128;
#pragma unroll
    for (int dd = 0; dd < 32; dd++) out[(size_t)(qp + 2 * dd) * 128 + n] = acc[dd];
}

// ---------------------------------------------------------------------------
// Kernel 2: scores GEMM partials (f32x2).
// jh=0: B = 0.5*K + (1/64)*KEO (on-the-fly re transform), from K input
// jh=1: B = Kt_im (materialized)
// grid (KCH=4, jh=2, bh=64), block 256, thread tile 8m x 8j, ktile 16
// ---------------------------------------------------------------------------
__global__ __launch_bounds__(256) void gemm_scores(const float* __restrict__ q,
                                                   const float* __restrict__ kin) {
    __shared__ __align__(16) float Qs[16][132];   // [kk][m]
    __shared__ __align__(16) float Kts[16][132];  // [kk][j]

    int kc = blockIdx.x;
    int jh = blockIdx.y;
    int bh = blockIdx.z;
    int b  = bh >> 4, h = bh & 15;
    int tid = threadIdx.x;
    int tr = tid >> 4, tc = tid & 15;

    ull c2[8][4];
    ull z = pack2(0.0f, 0.0f);
#pragma unroll
    for (int i = 0; i < 8; i++)
#pragma unroll
        for (int j = 0; j < 4; j++) c2[i][j] = z;

    const float* qbase   = q   + (size_t)b * (LDIM * ROWSTRIDE) + h * DDIM;
    const float* kbase   = kin + (size_t)b * (LDIM * ROWSTRIDE) + h * DDIM;
    const float* ktbase  = g_Kt  + (size_t)bh * KDIM * 128;
    const float* keobase = g_KEO + (size_t)bh * LSEG * MSEG * 2;
    int k0 = kc * (KDIM / KCH);

    for (int kt = 0; kt < (KDIM / KCH) / 16; kt++) {
        int kap = k0 + kt * 16;
        int l   = kap >> 6;
        int dst = kap & 63;

        // Q tile: 128 m x 16 kappa, transposed
#pragma unroll
        for (int i = 0; i < 2; i++) {
            int idx = tid + i * 256;
            int m = idx >> 2, q4 = idx & 3;
            float4 v = *(const float4*)(qbase + (size_t)(m * LSEG + l) * ROWSTRIDE + dst + q4 * 4);
            Qs[q4 * 4 + 0][m] = v.x;
            Qs[q4 * 4 + 1][m] = v.y;
            Qs[q4 * 4 + 2][m] = v.z;
            Qs[q4 * 4 + 3][m] = v.w;
        }
        if (jh == 0) {
            // re: transform K on the fly
#pragma unroll
            for (int i = 0; i < 2; i++) {
                int idx = tid + i * 256;
                int n = idx >> 2, ch = idx & 3;
                float4 kv = *(const float4*)(kbase + (size_t)(n * LSEG + l) * ROWSTRIDE + dst + ch * 4);
                float2 eo = *(const float2*)(keobase + ((size_t)l * 128 + n) * 2);
                Kts[ch * 4 + 0][n] = 0.5f * kv.x + (1.0f / 64.0f) * eo.x;
                Kts[ch * 4 + 1][n] = 0.5f * kv.y + (1.0f / 64.0f) * eo.y;
                Kts[ch * 4 + 2][n] = 0.5f * kv.z + (1.0f / 64.0f) * eo.x;
                Kts[ch * 4 + 3][n] = 0.5f * kv.w + (1.0f / 64.0f) * eo.y;
            }
        } else {
            // im: stream materialized Kt_im
#pragma unroll
            for (int i = 0; i < 2; i++) {
                int idx = tid + i * 256;
                int kk = idx >> 5, jq = idx & 31;
                float4 v = *(const float4*)(ktbase + (size_t)(kap + kk) * 128 + jq * 4);
                *(float4*)&Kts[kk][jq * 4] = v;
            }
        }
        __syncthreads();

#pragma unroll
        for (int kk = 0; kk < 16; kk++) {
            float4 a0 = *(const float4*)&Qs[kk][tr * 8];
            float4 a1 = *(const float4*)&Qs[kk][tr * 8 + 4];
            ulonglong2 bl0 = *(const ulonglong2*)&Kts[kk][tc * 8];
            ulonglong2 bl1 = *(const ulonglong2*)&Kts[kk][tc * 8 + 4];
            ull bb0 = bl0.x, bb1 = bl0.y, bb2 = bl1.x, bb3 = bl1.y;
            float aa[8] = {a0.x, a0.y, a0.z, a0.w, a1.x, a1.y, a1.z, a1.w};
#pragma unroll
            for (int i = 0; i < 8; i++) {
                ull ad = pack2(aa[i], aa[i]);
                ffma2(c2[i][0], ad, bb0);
                ffma2(c2[i][1], ad, bb1);
                ffma2(c2[i][2], ad, bb2);
                ffma2(c2[i][3], ad, bb3);
            }
        }
        __syncthreads();
    }

    float* cp = g_Cpart + ((size_t)kc * BH + bh) * (MSEG * 256) + (size_t)jh * 128;
#pragma unroll
    for (int i = 0; i < 8; i++) {
        int m = tr * 8 + i;
        float2 r0 = unpack2(c2[i][0]), r1 = unpack2(c2[i][1]);
        float2 r2 = unpack2(c2[i][2]), r3 = unpack2(c2[i][3]);
        *(float4*)(cp + (size_t)m * 256 + tc * 8)     = make_float4(r0.x, r0.y, r1.x, r1.y);
        *(float4*)(cp + (size_t)m * 256 + tc * 8 + 4) = make_float4(r2.x, r2.y, r3.x, r3.y);
    }
}

// ---------------------------------------------------------------------------
// Kernel 3: reduce partials, |S|/512, row softmax -> g_A
// grid (64, 16), block 256: warp per row, 8 rows per block
// ---------------------------------------------------------------------------
__global__ __launch_bounds__(256) void softmax_k() {
    int bh   = blockIdx.x;
    int m    = blockIdx.y * 8 + (threadIdx.x >> 5);
    int lane = threadIdx.x & 31;

    float t[4];
#pragma unroll
    for (int u = 0; u < 4; u++) {
        int n = lane + u * 32;
        float sre = 0.0f, sim = 0.0f;
#pragma unroll
        for (int p = 0; p < KCH; p++) {
            const float* cp = g_Cpart + (((size_t)p * BH + bh) * MSEG + m) * 256;
            sre += cp[n];
            sim += cp[n + 128];
        }
        t[u] = sqrtf(sre * sre + sim * sim) * (1.0f / 512.0f);
    }
    float mx = fmaxf(fmaxf(t[0], t[1]), fmaxf(t[2], t[3]));
#pragma unroll
    for (int o = 16; o; o >>= 1) mx = fmaxf(mx, __shfl_xor_sync(0xffffffffu, mx, o));
    float e[4], s = 0.0f;
#pragma unroll
    for (int u = 0; u < 4; u++) { e[u] = expf(t[u] - mx); s += e[u]; }
#pragma unroll
    for (int o = 16; o; o >>= 1) s += __shfl_xor_sync(0xffffffffu, s, o);
    float inv = 1.0f / s;
    float* arow = g_A + ((size_t)bh * MSEG + m) * MSEG;
#pragma unroll
    for (int u = 0; u < 4; u++) arow[lane + u * 32] = e[u] * inv;
}

// ---------------------------------------------------------------------------
// Kernel 4: out[m][l][d] = sum_n A[m][n] * v[n][l][d]  (f32x2, m-pair packed)
// grid 4096 = bh*64 + l, block 256, thread tile 8m x 4d, n chunked by 32
// ---------------------------------------------------------------------------
__global__ __launch_bounds__(256) void v_gemm(const float* __restrict__ v,
                                              float* __restrict__ out) {
    __shared__ __align__(16) float Ast[32][132];  // [n][m]
    __shared__ __align__(16) float vs[32][68];    // [n][d]

    int bx = blockIdx.x;
    int l  = bx & 63;
    int bh = bx >> 6;
    int b  = bh >> 4, h = bh & 15;
    int tid = threadIdx.x;
    int tr = tid >> 4, tc = tid & 15;

    ull c2[4][4];
    ull z = pack2(0.0f, 0.0f);
#pragma unroll
    for (int i = 0; i < 4; i++)
#pragma unroll
        for (int j = 0; j < 4; j++) c2[i][j] = z;

    const float* vbase = v + (size_t)b * (LDIM * ROWSTRIDE) + (size_t)l * ROWSTRIDE + h * DDIM;
    const float* Abase = g_A + (size_t)bh * MSEG * MSEG;

    for (int nc = 0; nc < 4; nc++) {
#pragma unroll
        for (int i = 0; i < 4; i++) {
            int idx = tid + i * 256;
            int m = idx >> 3, nq = idx & 7;
            float4 av = *(const float4*)(Abase + (size_t)m * MSEG + nc * 32 + nq * 4);
            Ast[nq * 4 + 0][m] = av.x;
            Ast[nq * 4 + 1][m] = av.y;
            Ast[nq * 4 + 2][m] = av.z;
            Ast[nq * 4 + 3][m] = av.w;
        }
#pragma unroll
        for (int i = 0; i < 2; i++) {
            int idx = tid + i * 256;
            int n = idx >> 4, dq = idx & 15;
            float4 vv = *(const float4*)(vbase + (size_t)(nc * 32 + n) * SEGSTRIDE + dq * 4);
            *(float4*)&vs[n][dq * 4] = vv;
        }
        __syncthreads();

#pragma unroll
        for (int nn = 0; nn < 32; nn++) {
            ulonglong2 av0 = *(const ulonglong2*)&Ast[nn][tr * 8];
            ulonglong2 av1 = *(const ulonglong2*)&Ast[nn][tr * 8 + 4];
            ull a20 = av0.x, a21 = av0.y, a22 = av1.x, a23 = av1.y;
            float4 bv = *(const float4*)&vs[nn][tc * 4];
            ull b20 = pack2(bv.x, bv.x);
            ull b21 = pack2(bv.y, bv.y);
            ull b22 = pack2(bv.z, bv.z);
            ull b23 = pack2(bv.w, bv.w);
            ffma2(c2[0][0], a20, b20); ffma2(c2[0][1], a20, b21);
            ffma2(c2[0][2], a20, b22); ffma2(c2[0][3], a20, b23);
            ffma2(c2[1][0], a21, b20); ffma2(c2[1][1], a21, b21);
            ffma2(c2[1][2], a21, b22); ffma2(c2[1][3], a21, b23);
            ffma2(c2[2][0], a22, b20); ffma2(c2[2][1], a22, b21);
            ffma2(c2[2][2], a22, b22); ffma2(c2[2][3], a22, b23);
            ffma2(c2[3][0], a23, b20); ffma2(c2[3][1], a23, b21);
            ffma2(c2[3][2], a23, b22); ffma2(c2[3][3], a23, b23);
        }
        __syncthreads();
    }

    float* obase = out + (size_t)b * (LDIM * ROWSTRIDE) + (size_t)l * ROWSTRIDE + h * DDIM;
#pragma unroll
    for (int i = 0; i < 4; i++) {
        float2 u0 = unpack2(c2[i][0]), u1 = unpack2(c2[i][1]);
        float2 u2 = unpack2(c2[i][2]), u3 = unpack2(c2[i][3]);
        int m0 = tr * 8 + 2 * i;
        *(float4*)(obase + (size_t)m0 * SEGSTRIDE + tc * 4)       = make_float4(u0.x, u1.x, u2.x, u3.x);
        *(float4*)(obase + (size_t)(m0 + 1) * SEGSTRIDE + tc * 4) = make_float4(u0.y, u1.y, u2.y, u3.y);
    }
}

// ---------------------------------------------------------------------------
extern "C" void kernel_launch(void* const* d_in, const int* in_sizes, int n_in,
                              void* d_out, int out_size) {
    const float* q = (const float*)d_in[0];
    const float* k = (const float*)d_in[1];
    const float* v = (const float*)d_in[2];
    float* out = (float*)d_out;

    build_ktim<<<BH * LSEG, 256>>>(k);
    gemm_scores<<<dim3(KCH, 2, BH), 256>>>(q, k);
    softmax_k<<<dim3(BH, 16), 256>>>();
    v_gemm<<<BH * LSEG, 256>>>(v, out);
}

// round 3
// speedup vs baseline: 2.2300x; 2.0587x over previous
#include <cuda_runtime.h>
#include <math.h>

// FourierAttention, FFT-free + TF32 tensor-core GEMMs (R3).
// B=4, L=8192, H=16, D=64, Ls=64, M=128.

#define BDIM 4
#define LDIM 8192
#define HDIM 16
#define DDIM 64
#define LSEG 64
#define MSEG 128
#define BH   64
#define KDIM 4096
#define KCH  4
#define ROWSTRIDE 1024
#define SEGSTRIDE 65536
#define BSTRIDE (LDIM*ROWSTRIDE)

// Scratch (device globals: allocation-free, graph-capture safe)
__device__ float g_Kt[(size_t)BH * LSEG * MSEG * DDIM];  // im-K, [bh][l][n][d], 134 MB
__device__ float g_KEO[(size_t)BH * LSEG * MSEG * 2];    // parity sums, [bh][l][n][2]
__device__ float g_Cpart[(size_t)KCH * BH * MSEG * 256]; // score partials
__device__ float g_A[(size_t)BH * MSEG * MSEG];          // softmax result

__device__ __forceinline__ float f2tf(float x) {
    unsigned u;
    asm("cvt.rna.tf32.f32 %0,%1;" : "=r"(u) : "f"(x));
    return __uint_as_float(u);
}

__device__ __forceinline__ void mma_tf32(float* d, const unsigned* a, const unsigned* b) {
    asm volatile(
        "mma.sync.aligned.m16n8k8.row.col.f32.tf32.tf32.f32 "
        "{%0,%1,%2,%3}, {%4,%5,%6,%7}, {%8,%9}, {%0,%1,%2,%3};"
        : "+f"(d[0]), "+f"(d[1]), "+f"(d[2]), "+f"(d[3])
        : "r"(a[0]), "r"(a[1]), "r"(a[2]), "r"(a[3]), "r"(b[0]), "r"(b[1]));
}

// ---------------------------------------------------------------------------
// Kernel 1: Kt_im[bh][l][n][d] + parity sums KEO[bh][l][n][par]
// grid 4096 = bh*64 + l, block 256.
// ---------------------------------------------------------------------------
__global__ __launch_bounds__(256) void build_ktim(const float* __restrict__ k) {
    __shared__ float sbuf[8704];   // reused: ks[64][129] then kts[128][68]
    __shared__ float ct[128];

    float (*ks)[129] = (float(*)[129])sbuf;

    int bx = blockIdx.x;
    int l  = bx & 63;
    int bh = bx >> 6;
    int b  = bh >> 4, h = bh & 15;
    int tid = threadIdx.x;

    const float* kbase = k + (size_t)b * BSTRIDE + (size_t)l * ROWSTRIDE + h * DDIM;

#pragma unroll
    for (int i = 0; i < 8; i++) {
        int idx = tid + i * 256;
        int n = idx >> 4, dq = idx & 15;
        float4 v = *(const float4*)(kbase + (size_t)n * SEGSTRIDE + dq * 4);
        ks[dq * 4 + 0][n] = v.x;
        ks[dq * 4 + 1][n] = v.y;
        ks[dq * 4 + 2][n] = v.z;
        ks[dq * 4 + 3][n] = v.w;
    }
    if (tid < 128) {
        int delta = tid - 64;
        float val = 0.0f;
        if (delta & 1) {
            float x = (float)delta * (1.0f / 64.0f);
            val = -(cospif(x) / sinpif(x)) * (1.0f / 64.0f);
        }
        ct[tid] = val;
    }
    __syncthreads();

    int n = tid & 127;
    int qp = tid >> 7;  // output-d parity

    // parity sum
    {
        float s = 0.0f;
#pragma unroll
        for (int t = 0; t < 32; t++) s += ks[2 * t + qp][n];
        g_KEO[(((size_t)bh * 64 + l) * 128 + n) * 2 + qp] = s;
    }

    // im correlation, taps in registers
    float ctr[63];
#pragma unroll
    for (int u = 0; u < 63; u++) ctr[u] = ct[2 * u + 2 * qp + 1];
    float acc[32];
#pragma unroll
    for (int dd = 0; dd < 32; dd++) acc[dd] = 0.0f;
#pragma unroll
    for (int t = 0; t < 32; t++) {
        float kv = ks[(1 - qp) + 2 * t][n];
#pragma unroll
        for (int dd = 0; dd < 32; dd++) acc[dd] += ctr[dd - t + 31] * kv;
    }
    __syncthreads();  // all ks reads done; reuse buffer

    float (*kts)[68] = (float(*)[68])sbuf;
#pragma unroll
    for (int dd = 0; dd < 32; dd++) kts[n][qp + 2 * dd] = acc[dd];
    __syncthreads();

    float* base = g_Kt + ((size_t)bh * 64 + l) * (128 * 64);
#pragma unroll
    for (int i = 0; i < 8; i++) {
        int idx = tid + i * 256;
        int n2 = idx >> 4, q4 = idx & 15;
        *(float4*)(base + (size_t)n2 * 64 + q4 * 4) = *(const float4*)&kts[n2][q4 * 4];
    }
}

// ---------------------------------------------------------------------------
// Kernel 2: scores GEMM partials via TF32 mma.sync.
// jh=0: B = 0.5*K + (1/64)*KEO (re, on the fly). jh=1: B = Kt_im.
// grid (KCH=4, jh=2, bh=64), block 256 (8 warps).
// Block tile 128m x 128j, Kblk=1024, ktile=32, warp tile 64m x 32j.
// ---------------------------------------------------------------------------
__global__ __launch_bounds__(256) void gemm_scores_tc(const float* __restrict__ q,
                                                      const float* __restrict__ kin) {
    __shared__ float As[128][36];
    __shared__ float Bs[128][36];

    int kc = blockIdx.x;
    int jh = blockIdx.y;
    int bh = blockIdx.z;
    int b  = bh >> 4, h = bh & 15;
    int tid  = threadIdx.x;
    int lane = tid & 31;
    int w    = tid >> 5;
    int g = lane >> 2, t = lane & 3;
    int m0 = (w >> 2) * 64;
    int j0 = (w & 3) * 32;

    float d[4][4][4];
#pragma unroll
    for (int mi = 0; mi < 4; mi++)
#pragma unroll
        for (int nj = 0; nj < 4; nj++)
#pragma unroll
            for (int r = 0; r < 4; r++) d[mi][nj][r] = 0.0f;

    const float* qb   = q   + (size_t)b * BSTRIDE + h * DDIM;
    const float* kb   = kin + (size_t)b * BSTRIDE + h * DDIM;
    const float* ktb  = g_Kt  + (size_t)bh * (64 * 128 * 64);
    const float* keob = g_KEO + (size_t)bh * (64 * 128 * 2);

    for (int kt = 0; kt < 32; kt++) {
        int kap = kc * 1024 + kt * 32;
        int l   = kap >> 6;
        int dst = kap & 63;

        // A tile: 128m x 32k from Q
#pragma unroll
        for (int i = 0; i < 4; i++) {
            int idx = tid + i * 256;
            int m = idx >> 3, kq = idx & 7;
            float4 v = *(const float4*)(qb + (size_t)(m * LSEG + l) * ROWSTRIDE + dst + kq * 4);
            float4 cv = make_float4(f2tf(v.x), f2tf(v.y), f2tf(v.z), f2tf(v.w));
            *(float4*)&As[m][kq * 4] = cv;
        }
        // B tile: 128j x 32k
        if (jh == 0) {
#pragma unroll
            for (int i = 0; i < 4; i++) {
                int idx = tid + i * 256;
                int n = idx >> 3, kq = idx & 7;
                float4 kv = *(const float4*)(kb + (size_t)(n * LSEG + l) * ROWSTRIDE + dst + kq * 4);
                float2 eo = *(const float2*)(keob + ((size_t)l * 128 + n) * 2);
                float4 cv = make_float4(
                    f2tf(0.5f * kv.x + (1.0f / 64.0f) * eo.x),
                    f2tf(0.5f * kv.y + (1.0f / 64.0f) * eo.y),
                    f2tf(0.5f * kv.z + (1.0f / 64.0f) * eo.x),
                    f2tf(0.5f * kv.w + (1.0f / 64.0f) * eo.y));
                *(float4*)&Bs[n][kq * 4] = cv;
            }
        } else {
#pragma unroll
            for (int i = 0; i < 4; i++) {
                int idx = tid + i * 256;
                int n = idx >> 3, kq = idx & 7;
                float4 v = *(const float4*)(ktb + ((size_t)l * 128 + n) * 64 + dst + kq * 4);
                float4 cv = make_float4(f2tf(v.x), f2tf(v.y), f2tf(v.z), f2tf(v.w));
                *(float4*)&Bs[n][kq * 4] = cv;
            }
        }
        __syncthreads();

#pragma unroll
        for (int s = 0; s < 4; s++) {
            int k8 = s * 8;
            unsigned a[4][4];
#pragma unroll
            for (int mi = 0; mi < 4; mi++) {
                int r = m0 + mi * 16 + g;
                a[mi][0] = __float_as_uint(As[r][k8 + t]);
                a[mi][1] = __float_as_uint(As[r + 8][k8 + t]);
                a[mi][2] = __float_as_uint(As[r][k8 + 4 + t]);
                a[mi][3] = __float_as_uint(As[r + 8][k8 + 4 + t]);
            }
            unsigned bb[4][2];
#pragma unroll
            for (int nj = 0; nj < 4; nj++) {
                int c = j0 + nj * 8 + g;
                bb[nj][0] = __float_as_uint(Bs[c][k8 + t]);
                bb[nj][1] = __float_as_uint(Bs[c][k8 + 4 + t]);
            }
#pragma unroll
            for (int mi = 0; mi < 4; mi++)
#pragma unroll
                for (int nj = 0; nj < 4; nj++) mma_tf32(d[mi][nj], a[mi], bb[nj]);
        }
        __syncthreads();
    }

    float* cp = g_Cpart + ((size_t)(kc * BH + bh) * MSEG) * 256 + (size_t)jh * 128;
#pragma unroll
    for (int mi = 0; mi < 4; mi++) {
#pragma unroll
        for (int nj = 0; nj < 4; nj++) {
            int r = m0 + mi * 16 + g;
            int c = j0 + nj * 8 + 2 * t;
            *(float2*)(cp + (size_t)r * 256 + c)       = make_float2(d[mi][nj][0], d[mi][nj][1]);
            *(float2*)(cp + (size_t)(r + 8) * 256 + c) = make_float2(d[mi][nj][2], d[mi][nj][3]);
        }
    }
}

// ---------------------------------------------------------------------------
// Kernel 3: reduce partials, |S|/512, row softmax -> g_A
// grid (64, 16), block 256: warp per row
// ---------------------------------------------------------------------------
__global__ __launch_bounds__(256) void softmax_k() {
    int bh   = blockIdx.x;
    int m    = blockIdx.y * 8 + (threadIdx.x >> 5);
    int lane = threadIdx.x & 31;

    float t[4];
#pragma unroll
    for (int u = 0; u < 4; u++) {
        int n = lane + u * 32;
        float sre = 0.0f, sim = 0.0f;
#pragma unroll
        for (int p = 0; p < KCH; p++) {
            const float* cp = g_Cpart + (((size_t)p * BH + bh) * MSEG + m) * 256;
            sre += cp[n];
            sim += cp[n + 128];
        }
        t[u] = sqrtf(sre * sre + sim * sim) * (1.0f / 512.0f);
    }
    float mx = fmaxf(fmaxf(t[0], t[1]), fmaxf(t[2], t[3]));
#pragma unroll
    for (int o = 16; o; o >>= 1) mx = fmaxf(mx, __shfl_xor_sync(0xffffffffu, mx, o));
    float e[4], s = 0.0f;
#pragma unroll
    for (int u = 0; u < 4; u++) { e[u] = expf(t[u] - mx); s += e[u]; }
#pragma unroll
    for (int o = 16; o; o >>= 1) s += __shfl_xor_sync(0xffffffffu, s, o);
    float inv = 1.0f / s;
    float* arow = g_A + ((size_t)bh * MSEG + m) * MSEG;
#pragma unroll
    for (int u = 0; u < 4; u++) arow[lane + u * 32] = e[u] * inv;
}

// ---------------------------------------------------------------------------
// Kernel 4: out[m][l][d] = sum_n A[m][n] * v[n][l][d] via TF32 mma.sync.
// grid 4096 = bh*64 + l, block 256 (8 warps), block tile 128m x 64d,
// warp tile 32m x 32d, K=128 in 4 chunks of 32. No operand transposes.
// ---------------------------------------------------------------------------
__global__ __launch_bounds__(256) void v_gemm_tc(const float* __restrict__ v,
                                                 float* __restrict__ out) {
    __shared__ float As[128][36];   // A_attn chunk [m][n]
    __shared__ float vs[32][72];    // v chunk [n][d]

    int bx = blockIdx.x;
    int l  = bx & 63;
    int bh = bx >> 6;
    int b  = bh >> 4, h = bh & 15;
    int tid  = threadIdx.x;
    int lane = tid & 31;
    int w    = tid >> 5;
    int g = lane >> 2, t = lane & 3;
    int m0 = (w >> 1) * 32;
    int d0 = (w & 1) * 32;

    float d[2][4][4];
#pragma unroll
    for (int mi = 0; mi < 2; mi++)
#pragma unroll
        for (int dj = 0; dj < 4; dj++)
#pragma unroll
            for (int r = 0; r < 4; r++) d[mi][dj][r] = 0.0f;

    const float* vbase = v + (size_t)b * BSTRIDE + (size_t)l * ROWSTRIDE + h * DDIM;
    const float* Abase = g_A + (size_t)bh * MSEG * MSEG;

    for (int nc = 0; nc < 4; nc++) {
        int n0c = nc * 32;
        // A chunk: 128m x 32n
#pragma unroll
        for (int i = 0; i < 4; i++) {
            int idx = tid + i * 256;
            int m = idx >> 3, kq = idx & 7;
            float4 av = *(const float4*)(Abase + (size_t)m * MSEG + n0c + kq * 4);
            float4 cv = make_float4(f2tf(av.x), f2tf(av.y), f2tf(av.z), f2tf(av.w));
            *(float4*)&As[m][kq * 4] = cv;
        }
        // v chunk: 32n x 64d
#pragma unroll
        for (int i = 0; i < 2; i++) {
            int idx = tid + i * 256;
            int n = idx >> 4, dq = idx & 15;
            float4 vv = *(const float4*)(vbase + (size_t)(n0c + n) * SEGSTRIDE + dq * 4);
            float4 cv = make_float4(f2tf(vv.x), f2tf(vv.y), f2tf(vv.z), f2tf(vv.w));
            *(float4*)&vs[n][dq * 4] = cv;
        }
        __syncthreads();

#pragma unroll
        for (int s = 0; s < 4; s++) {
            int k8 = s * 8;
            unsigned a[2][4];
#pragma unroll
            for (int mi = 0; mi < 2; mi++) {
                int r = m0 + mi * 16 + g;
                a[mi][0] = __float_as_uint(As[r][k8 + t]);
                a[mi][1] = __float_as_uint(As[r + 8][k8 + t]);
                a[mi][2] = __float_as_uint(As[r][k8 + 4 + t]);
                a[mi][3] = __float_as_uint(As[r + 8][k8 + 4 + t]);
            }
            unsigned bb[4][2];
#pragma unroll
            for (int dj = 0; dj < 4; dj++) {
                int c = d0 + dj * 8 + g;
                bb[dj][0] = __float_as_uint(vs[k8 + t][c]);
                bb[dj][1] = __float_as_uint(vs[k8 + 4 + t][c]);
            }
#pragma unroll
            for (int mi = 0; mi < 2; mi++)
#pragma unroll
                for (int dj = 0; dj < 4; dj++) mma_tf32(d[mi][dj], a[mi], bb[dj]);
        }
        __syncthreads();
    }

    float* obase = out + (size_t)b * BSTRIDE + (size_t)l * ROWSTRIDE + h * DDIM;
#pragma unroll
    for (int mi = 0; mi < 2; mi++) {
#pragma unroll
        for (int dj = 0; dj < 4; dj++) {
            int r = m0 + mi * 16 + g;
            int c = d0 + dj * 8 + 2 * t;
            *(float2*)(obase + (size_t)r * SEGSTRIDE + c)       = make_float2(d[mi][dj][0], d[mi][dj][1]);
            *(float2*)(obase + (size_t)(r + 8) * SEGSTRIDE + c) = make_float2(d[mi][dj][2], d[mi][dj][3]);
        }
    }
}

// ---------------------------------------------------------------------------
extern "C" void kernel_launch(void* const* d_in, const int* in_sizes, int n_in,
                              void* d_out, int out_size) {
    const float* q = (const float*)d_in[0];
    const float* k = (const float*)d_in[1];
    const float* v = (const float*)d_in[2];
    float* out = (float*)d_out;

    build_ktim<<<BH * LSEG, 256>>>(k);
    gemm_scores_tc<<<dim3(KCH, 2, BH), 256>>>(q, k);
    softmax_k<<<dim3(BH, 16), 256>>>();
    v_gemm_tc<<<BH * LSEG, 256>>>(v, out);
}

// round 4
// speedup vs baseline: 2.5077x; 1.1245x over previous
#include <cuda_runtime.h>
#include <math.h>

// FourierAttention, FFT-free + TF32 tensor cores + reg-double-buffered pipeline (R4).
// B=4, L=8192, H=16, D=64, Ls=64, M=128.

#define BDIM 4
#define LDIM 8192
#define HDIM 16
#define DDIM 64
#define LSEG 64
#define MSEG 128
#define BH   64
#define KDIM 4096
#define KCH  4
#define ROWSTRIDE 1024
#define SEGSTRIDE 65536
#define BSTRIDE (LDIM*ROWSTRIDE)

// Scratch (device globals: allocation-free, graph-capture safe)
__device__ float g_Kt[(size_t)BH * LSEG * MSEG * DDIM];  // im-K, [bh][l][n][d]
__device__ float g_KEO[(size_t)BH * LSEG * MSEG * 2];    // parity sums, [bh][l][n][2]
__device__ float g_Cpart[(size_t)KCH * BH * MSEG * 256]; // score partials
__device__ float g_A[(size_t)BH * MSEG * MSEG];          // softmax result

__device__ __forceinline__ float f2tf(float x) {
    unsigned u;
    asm("cvt.rna.tf32.f32 %0,%1;" : "=r"(u) : "f"(x));
    return __uint_as_float(u);
}

__device__ __forceinline__ void mma_tf32(float* d, const unsigned* a, const unsigned* b) {
    asm volatile(
        "mma.sync.aligned.m16n8k8.row.col.f32.tf32.tf32.f32 "
        "{%0,%1,%2,%3}, {%4,%5,%6,%7}, {%8,%9}, {%0,%1,%2,%3};"
        : "+f"(d[0]), "+f"(d[1]), "+f"(d[2]), "+f"(d[3])
        : "r"(a[0]), "r"(a[1]), "r"(a[2]), "r"(a[3]), "r"(b[0]), "r"(b[1]));
}

// ---------------------------------------------------------------------------
// Kernel 1: Kt_im[bh][l][n][d] + parity sums KEO[bh][l][n][par]
// ---------------------------------------------------------------------------
__global__ __launch_bounds__(256) void build_ktim(const float* __restrict__ k) {
    __shared__ float sbuf[8704];   // reused: ks[64][129] then kts[128][68]
    __shared__ float ct[128];

    float (*ks)[129] = (float(*)[129])sbuf;

    int bx = blockIdx.x;
    int l  = bx & 63;
    int bh = bx >> 6;
    int b  = bh >> 4, h = bh & 15;
    int tid = threadIdx.x;

    const float* kbase = k + (size_t)b * BSTRIDE + (size_t)l * ROWSTRIDE + h * DDIM;

#pragma unroll
    for (int i = 0; i < 8; i++) {
        int idx = tid + i * 256;
        int n = idx >> 4, dq = idx & 15;
        float4 v = *(const float4*)(kbase + (size_t)n * SEGSTRIDE + dq * 4);
        ks[dq * 4 + 0][n] = v.x;
        ks[dq * 4 + 1][n] = v.y;
        ks[dq * 4 + 2][n] = v.z;
        ks[dq * 4 + 3][n] = v.w;
    }
    if (tid < 128) {
        int delta = tid - 64;
        float val = 0.0f;
        if (delta & 1) {
            float x = (float)delta * (1.0f / 64.0f);
            val = -(cospif(x) / sinpif(x)) * (1.0f / 64.0f);
        }
        ct[tid] = val;
    }
    __syncthreads();

    int n = tid & 127;
    int qp = tid >> 7;

    {
        float s = 0.0f;
#pragma unroll
        for (int t = 0; t < 32; t++) s += ks[2 * t + qp][n];
        g_KEO[(((size_t)bh * 64 + l) * 128 + n) * 2 + qp] = s;
    }

    float ctr[63];
#pragma unroll
    for (int u = 0; u < 63; u++) ctr[u] = ct[2 * u + 2 * qp + 1];
    float acc[32];
#pragma unroll
    for (int dd = 0; dd < 32; dd++) acc[dd] = 0.0f;
#pragma unroll
    for (int t = 0; t < 32; t++) {
        float kv = ks[(1 - qp) + 2 * t][n];
#pragma unroll
        for (int dd = 0; dd < 32; dd++) acc[dd] += ctr[dd - t + 31] * kv;
    }
    __syncthreads();

    float (*kts)[68] = (float(*)[68])sbuf;
#pragma unroll
    for (int dd = 0; dd < 32; dd++) kts[n][qp + 2 * dd] = acc[dd];
    __syncthreads();

    float* base = g_Kt + ((size_t)bh * 64 + l) * (128 * 64);
#pragma unroll
    for (int i = 0; i < 8; i++) {
        int idx = tid + i * 256;
        int n2 = idx >> 4, q4 = idx & 15;
        *(float4*)(base + (size_t)n2 * 64 + q4 * 4) = *(const float4*)&kts[n2][q4 * 4];
    }
}

// ---------------------------------------------------------------------------
// Kernel 2: scores GEMM partials via TF32 mma.sync, reg double-buffered.
// jh=0: B = 0.5*K + (1/64)*KEO (re, on the fly). jh=1: B = Kt_im.
// grid (KCH=4, jh=2, bh=64), block 256 (8 warps), tile 128x128, ktile 32.
// ---------------------------------------------------------------------------
__global__ __launch_bounds__(256, 2) void gemm_scores_tc(const float* __restrict__ q,
                                                         const float* __restrict__ kin) {
    __shared__ float As[128][36];
    __shared__ float Bs[128][36];

    int kc = blockIdx.x;
    int jh = blockIdx.y;
    int bh = blockIdx.z;
    int b  = bh >> 4, h = bh & 15;
    int tid  = threadIdx.x;
    int lane = tid & 31;
    int w    = tid >> 5;
    int g = lane >> 2, t = lane & 3;
    int m0 = (w >> 2) * 64;
    int j0 = (w & 3) * 32;

    float dacc[4][4][4];
#pragma unroll
    for (int mi = 0; mi < 4; mi++)
#pragma unroll
        for (int nj = 0; nj < 4; nj++)
#pragma unroll
            for (int r = 0; r < 4; r++) dacc[mi][nj][r] = 0.0f;

    const float* qb   = q   + (size_t)b * BSTRIDE + h * DDIM;
    const float* kb   = kin + (size_t)b * BSTRIDE + h * DDIM;
    const float* ktb  = g_Kt  + (size_t)bh * (64 * 128 * 64);
    const float* keob = g_KEO + (size_t)bh * (64 * 128 * 2);

    int mA[4], kqA[4];
#pragma unroll
    for (int i = 0; i < 4; i++) { int idx = tid + i * 256; mA[i] = idx >> 3; kqA[i] = idx & 7; }

    float4 ar[4], br[4];

    // prologue: load tile kt=0
    {
        int kap = kc * 1024;
        int l = kap >> 6, dst = kap & 63;
#pragma unroll
        for (int i = 0; i < 4; i++)
            ar[i] = *(const float4*)(qb + (size_t)(mA[i] * LSEG + l) * ROWSTRIDE + dst + kqA[i] * 4);
        if (jh == 0) {
#pragma unroll
            for (int i = 0; i < 4; i++)
                br[i] = *(const float4*)(kb + (size_t)(mA[i] * LSEG + l) * ROWSTRIDE + dst + kqA[i] * 4);
        } else {
#pragma unroll
            for (int i = 0; i < 4; i++)
                br[i] = *(const float4*)(ktb + ((size_t)l * 128 + mA[i]) * 64 + dst + kqA[i] * 4);
        }
    }

    for (int kt = 0; kt < 32; kt++) {
        int lcur = (kc * 1024 + kt * 32) >> 6;
        __syncthreads();
        // STS with cvt (+ re-transform on jh=0)
#pragma unroll
        for (int i = 0; i < 4; i++) {
            *(float4*)&As[mA[i]][kqA[i] * 4] =
                make_float4(f2tf(ar[i].x), f2tf(ar[i].y), f2tf(ar[i].z), f2tf(ar[i].w));
        }
        if (jh == 0) {
#pragma unroll
            for (int i = 0; i < 4; i++) {
                float2 eo = *(const float2*)(keob + ((size_t)lcur * 128 + mA[i]) * 2);
                *(float4*)&Bs[mA[i]][kqA[i] * 4] = make_float4(
                    f2tf(0.5f * br[i].x + (1.0f / 64.0f) * eo.x),
                    f2tf(0.5f * br[i].y + (1.0f / 64.0f) * eo.y),
                    f2tf(0.5f * br[i].z + (1.0f / 64.0f) * eo.x),
                    f2tf(0.5f * br[i].w + (1.0f / 64.0f) * eo.y));
            }
        } else {
#pragma unroll
            for (int i = 0; i < 4; i++) {
                *(float4*)&Bs[mA[i]][kqA[i] * 4] =
                    make_float4(f2tf(br[i].x), f2tf(br[i].y), f2tf(br[i].z), f2tf(br[i].w));
            }
        }
        __syncthreads();

        // prefetch next tile into regs (consumed after next sync)
        if (kt + 1 < 32) {
            int kap = kc * 1024 + (kt + 1) * 32;
            int l = kap >> 6, dst = kap & 63;
#pragma unroll
            for (int i = 0; i < 4; i++)
                ar[i] = *(const float4*)(qb + (size_t)(mA[i] * LSEG + l) * ROWSTRIDE + dst + kqA[i] * 4);
            if (jh == 0) {
#pragma unroll
                for (int i = 0; i < 4; i++)
                    br[i] = *(const float4*)(kb + (size_t)(mA[i] * LSEG + l) * ROWSTRIDE + dst + kqA[i] * 4);
            } else {
#pragma unroll
                for (int i = 0; i < 4; i++)
                    br[i] = *(const float4*)(ktb + ((size_t)l * 128 + mA[i]) * 64 + dst + kqA[i] * 4);
            }
        }

        // MMA over the smem tile
#pragma unroll
        for (int s = 0; s < 4; s++) {
            int k8 = s * 8;
            unsigned bb[4][2];
#pragma unroll
            for (int nj = 0; nj < 4; nj++) {
                int c = j0 + nj * 8 + g;
                bb[nj][0] = __float_as_uint(Bs[c][k8 + t]);
                bb[nj][1] = __float_as_uint(Bs[c][k8 + 4 + t]);
            }
#pragma unroll
            for (int mi = 0; mi < 4; mi++) {
                int r = m0 + mi * 16 + g;
                unsigned a[4];
                a[0] = __float_as_uint(As[r][k8 + t]);
                a[1] = __float_as_uint(As[r + 8][k8 + t]);
                a[2] = __float_as_uint(As[r][k8 + 4 + t]);
                a[3] = __float_as_uint(As[r + 8][k8 + 4 + t]);
#pragma unroll
                for (int nj = 0; nj < 4; nj++) mma_tf32(dacc[mi][nj], a, bb[nj]);
            }
        }
    }

    float* cp = g_Cpart + ((size_t)(kc * BH + bh) * MSEG) * 256 + (size_t)jh * 128;
#pragma unroll
    for (int mi = 0; mi < 4; mi++) {
#pragma unroll
        for (int nj = 0; nj < 4; nj++) {
            int r = m0 + mi * 16 + g;
            int c = j0 + nj * 8 + 2 * t;
            *(float2*)(cp + (size_t)r * 256 + c)       = make_float2(dacc[mi][nj][0], dacc[mi][nj][1]);
            *(float2*)(cp + (size_t)(r + 8) * 256 + c) = make_float2(dacc[mi][nj][2], dacc[mi][nj][3]);
        }
    }
}

// ---------------------------------------------------------------------------
// Kernel 3: reduce partials, |S|/512, row softmax -> g_A
// ---------------------------------------------------------------------------
__global__ __launch_bounds__(256) void softmax_k() {
    int bh   = blockIdx.x;
    int m    = blockIdx.y * 8 + (threadIdx.x >> 5);
    int lane = threadIdx.x & 31;

    float t[4];
#pragma unroll
    for (int u = 0; u < 4; u++) {
        int n = lane + u * 32;
        float sre = 0.0f, sim = 0.0f;
#pragma unroll
        for (int p = 0; p < KCH; p++) {
            const float* cp = g_Cpart + (((size_t)p * BH + bh) * MSEG + m) * 256;
            sre += cp[n];
            sim += cp[n + 128];
        }
        t[u] = sqrtf(sre * sre + sim * sim) * (1.0f / 512.0f);
    }
    float mx = fmaxf(fmaxf(t[0], t[1]), fmaxf(t[2], t[3]));
#pragma unroll
    for (int o = 16; o; o >>= 1) mx = fmaxf(mx, __shfl_xor_sync(0xffffffffu, mx, o));
    float e[4], s = 0.0f;
#pragma unroll
    for (int u = 0; u < 4; u++) { e[u] = expf(t[u] - mx); s += e[u]; }
#pragma unroll
    for (int o = 16; o; o >>= 1) s += __shfl_xor_sync(0xffffffffu, s, o);
    float inv = 1.0f / s;
    float* arow = g_A + ((size_t)bh * MSEG + m) * MSEG;
#pragma unroll
    for (int u = 0; u < 4; u++) arow[lane + u * 32] = e[u] * inv;
}

// ---------------------------------------------------------------------------
// Kernel 4: out[m][l][d] = sum_n A[m][n] * v[n][l][d], TF32 mma, reg pipelined.
// grid 4096 = bh*64 + l, block 256 (8 warps), tile 128m x 64d, 4 n-chunks of 32.
// ---------------------------------------------------------------------------
__global__ __launch_bounds__(256, 2) void v_gemm_tc(const float* __restrict__ v,
                                                    float* __restrict__ out) {
    __shared__ float As[128][36];   // A_attn chunk [m][n]
    __shared__ float vs[32][72];    // v chunk [n][d]

    int bx = blockIdx.x;
    int l  = bx & 63;
    int bh = bx >> 6;
    int b  = bh >> 4, h = bh & 15;
    int tid  = threadIdx.x;
    int lane = tid & 31;
    int w    = tid >> 5;
    int g = lane >> 2, t = lane & 3;
    int m0 = (w >> 1) * 32;
    int d0 = (w & 1) * 32;

    float dacc[2][4][4];
#pragma unroll
    for (int mi = 0; mi < 2; mi++)
#pragma unroll
        for (int dj = 0; dj < 4; dj++)
#pragma unroll
            for (int r = 0; r < 4; r++) dacc[mi][dj][r] = 0.0f;

    const float* vbase = v + (size_t)b * BSTRIDE + (size_t)l * ROWSTRIDE + h * DDIM;
    const float* Abase = g_A + (size_t)bh * MSEG * MSEG;

    int mA[4], kqA[4];
#pragma unroll
    for (int i = 0; i < 4; i++) { int idx = tid + i * 256; mA[i] = idx >> 3; kqA[i] = idx & 7; }
    int nV[2], dqV[2];
#pragma unroll
    for (int i = 0; i < 2; i++) { int idx = tid + i * 256; nV[i] = idx >> 4; dqV[i] = idx & 15; }

    float4 ar[4], vr[2];

    // prologue: chunk 0
#pragma unroll
    for (int i = 0; i < 4; i++)
        ar[i] = *(const float4*)(Abase + (size_t)mA[i] * MSEG + kqA[i] * 4);
#pragma unroll
    for (int i = 0; i < 2; i++)
        vr[i] = *(const float4*)(vbase + (size_t)nV[i] * SEGSTRIDE + dqV[i] * 4);

    for (int nc = 0; nc < 4; nc++) {
        __syncthreads();
#pragma unroll
        for (int i = 0; i < 4; i++) {
            *(float4*)&As[mA[i]][kqA[i] * 4] =
                make_float4(f2tf(ar[i].x), f2tf(ar[i].y), f2tf(ar[i].z), f2tf(ar[i].w));
        }
#pragma unroll
        for (int i = 0; i < 2; i++) {
            *(float4*)&vs[nV[i]][dqV[i] * 4] =
                make_float4(f2tf(vr[i].x), f2tf(vr[i].y), f2tf(vr[i].z), f2tf(vr[i].w));
        }
        __syncthreads();

        if (nc + 1 < 4) {
            int n0n = (nc + 1) * 32;
#pragma unroll
            for (int i = 0; i < 4; i++)
                ar[i] = *(const float4*)(Abase + (size_t)mA[i] * MSEG + n0n + kqA[i] * 4);
#pragma unroll
            for (int i = 0; i < 2; i++)
                vr[i] = *(const float4*)(vbase + (size_t)(n0n + nV[i]) * SEGSTRIDE + dqV[i] * 4);
        }

#pragma unroll
        for (int s = 0; s < 4; s++) {
            int k8 = s * 8;
            unsigned bb[4][2];
#pragma unroll
            for (int dj = 0; dj < 4; dj++) {
                int c = d0 + dj * 8 + g;
                bb[dj][0] = __float_as_uint(vs[k8 + t][c]);
                bb[dj][1] = __float_as_uint(vs[k8 + 4 + t][c]);
            }
#pragma unroll
            for (int mi = 0; mi < 2; mi++) {
                int r = m0 + mi * 16 + g;
                unsigned a[4];
                a[0] = __float_as_uint(As[r][k8 + t]);
                a[1] = __float_as_uint(As[r + 8][k8 + t]);
                a[2] = __float_as_uint(As[r][k8 + 4 + t]);
                a[3] = __float_as_uint(As[r + 8][k8 + 4 + t]);
#pragma unroll
                for (int dj = 0; dj < 4; dj++) mma_tf32(dacc[mi][dj], a, bb[dj]);
            }
        }
    }

    float* obase = out + (size_t)b * BSTRIDE + (size_t)l * ROWSTRIDE + h * DDIM;
#pragma unroll
    for (int mi = 0; mi < 2; mi++) {
#pragma unroll
        for (int dj = 0; dj < 4; dj++) {
            int r = m0 + mi * 16 + g;
            int c = d0 + dj * 8 + 2 * t;
            *(float2*)(obase + (size_t)r * SEGSTRIDE + c)       = make_float2(dacc[mi][dj][0], dacc[mi][dj][1]);
            *(float2*)(obase + (size_t)(r + 8) * SEGSTRIDE + c) = make_float2(dacc[mi][dj][2], dacc[mi][dj][3]);
        }
    }
}

// ---------------------------------------------------------------------------
extern "C" void kernel_launch(void* const* d_in, const int* in_sizes, int n_in,
                              void* d_out, int out_size) {
    const float* q = (const float*)d_in[0];
    const float* k = (const float*)d_in[1];
    const float* v = (const float*)d_in[2];
    float* out = (float*)d_out;

    build_ktim<<<BH * LSEG, 256>>>(k);
    gemm_scores_tc<<<dim3(KCH, 2, BH), 256>>>(q, k);
    softmax_k<<<dim3(BH, 16), 256>>>();
    v_gemm_tc<<<BH * LSEG, 256>>>(v, out);
}

// round 6
// speedup vs baseline: 2.8242x; 1.1262x over previous
#include <cuda_runtime.h>
#include <cuda_fp16.h>
#include <math.h>
#include <stdint.h>

// FourierAttention R6: FFT-free + FP16 mma.sync (m16n8k16, fp32 accum).
// tcgen05 is unavailable (harness PTX target is compute_103, not sm_103a).
// B=4, L=8192, H=16, D=64, Ls=64, M=128.

#define BDIM 4
#define LDIM 8192
#define HDIM 16
#define DDIM 64
#define LSEG 64
#define MSEG 128
#define BH   64
#define KDIM 4096
#define KCH  4
#define ROWSTRIDE 1024
#define SEGSTRIDE 65536
#define BSTRIDE (LDIM*ROWSTRIDE)

// Scratch (device globals: allocation-free, graph-capture safe)
__device__ __half g_KtH[(size_t)BH * LSEG * MSEG * DDIM]; // im-K, [bh][l][n][d], half
__device__ float g_KEO[(size_t)BH * LSEG * MSEG * 2];     // parity sums, [bh][l][n][2]
__device__ float g_Cpart[(size_t)KCH * BH * MSEG * 256];  // score partials
__device__ float g_A[(size_t)BH * MSEG * MSEG];           // softmax result

__device__ __forceinline__ void mma_f16(float* d, const unsigned* a, const unsigned* b) {
    asm volatile(
        "mma.sync.aligned.m16n8k16.row.col.f32.f16.f16.f32 "
        "{%0,%1,%2,%3},{%4,%5,%6,%7},{%8,%9},{%0,%1,%2,%3};"
        : "+f"(d[0]), "+f"(d[1]), "+f"(d[2]), "+f"(d[3])
        : "r"(a[0]), "r"(a[1]), "r"(a[2]), "r"(a[3]), "r"(b[0]), "r"(b[1]));
}

__device__ __forceinline__ unsigned h2u(float a, float b) {
    __half2 h = __floats2half2_rn(a, b);
    return *(unsigned*)&h;
}

// ---------------------------------------------------------------------------
// Kernel 1: Kt_im[bh][l][n][d] (half) + parity sums KEO[bh][l][n][par] (float)
// grid 4096 = bh*64 + l, block 256.
// ---------------------------------------------------------------------------
__global__ __launch_bounds__(256) void build_ktim(const float* __restrict__ k) {
    __shared__ float sbuf[8704];   // ks[64][129] then kts[128][68]
    __shared__ float ct[128];
    float (*ks)[129] = (float(*)[129])sbuf;

    int bx = blockIdx.x;
    int l  = bx & 63;
    int bh = bx >> 6;
    int b  = bh >> 4, h = bh & 15;
    int tid = threadIdx.x;

    const float* kbase = k + (size_t)b * BSTRIDE + (size_t)l * ROWSTRIDE + h * DDIM;

#pragma unroll
    for (int i = 0; i < 8; i++) {
        int idx = tid + i * 256;
        int n = idx >> 4, dq = idx & 15;
        float4 v = *(const float4*)(kbase + (size_t)n * SEGSTRIDE + dq * 4);
        ks[dq * 4 + 0][n] = v.x;
        ks[dq * 4 + 1][n] = v.y;
        ks[dq * 4 + 2][n] = v.z;
        ks[dq * 4 + 3][n] = v.w;
    }
    if (tid < 128) {
        int delta = tid - 64;
        float val = 0.0f;
        if (delta & 1) {
            float x = (float)delta * (1.0f / 64.0f);
            val = -(cospif(x) / sinpif(x)) * (1.0f / 64.0f);
        }
        ct[tid] = val;
    }
    __syncthreads();

    int n = tid & 127;
    int qp = tid >> 7;
    {
        float s = 0.0f;
#pragma unroll
        for (int t = 0; t < 32; t++) s += ks[2 * t + qp][n];
        g_KEO[(((size_t)bh * 64 + l) * 128 + n) * 2 + qp] = s;
    }
    float ctr[63];
#pragma unroll
    for (int u = 0; u < 63; u++) ctr[u] = ct[2 * u + 2 * qp + 1];
    float acc[32];
#pragma unroll
    for (int dd = 0; dd < 32; dd++) acc[dd] = 0.0f;
#pragma unroll
    for (int t = 0; t < 32; t++) {
        float kv = ks[(1 - qp) + 2 * t][n];
#pragma unroll
        for (int dd = 0; dd < 32; dd++) acc[dd] += ctr[dd - t + 31] * kv;
    }
    __syncthreads();
    float (*kts)[68] = (float(*)[68])sbuf;
#pragma unroll
    for (int dd = 0; dd < 32; dd++) kts[n][qp + 2 * dd] = acc[dd];
    __syncthreads();

    // write as half, [n][d] contiguous in d
    __half* base = g_KtH + ((size_t)bh * 64 + l) * (128 * 64);
#pragma unroll
    for (int i = 0; i < 4; i++) {
        int idx = tid + i * 256;            // 0..1023
        int n2 = idx >> 3, q8 = idx & 7;    // 8 halves per unit
        const float* src = &kts[n2][q8 * 8];
        uint4 u;
        u.x = h2u(src[0], src[1]);
        u.y = h2u(src[2], src[3]);
        u.z = h2u(src[4], src[5]);
        u.w = h2u(src[6], src[7]);
        *(uint4*)(base + (size_t)n2 * 64 + q8 * 8) = u;
    }
}

// ---------------------------------------------------------------------------
// Kernel 2: scores GEMM partials via FP16 mma.sync, reg double-buffered.
// jh=0: B = 0.5*K + (1/64)*KEO (fp32 transform, rounded at STS). jh=1: B = KtH.
// grid (KCH=4, jh=2, bh=64), block 256 (8 warps), tile 128x128, ktile 32.
// ---------------------------------------------------------------------------
__global__ __launch_bounds__(256, 2) void gemm_scores_h(const float* __restrict__ q,
                                                        const float* __restrict__ kin) {
    __shared__ __align__(16) __half As[128][40];
    __shared__ __align__(16) __half Bs[128][40];

    int kc = blockIdx.x;
    int jh = blockIdx.y;
    int bh = blockIdx.z;
    int b  = bh >> 4, h = bh & 15;
    int tid  = threadIdx.x;
    int lane = tid & 31;
    int w    = tid >> 5;
    int g = lane >> 2, t = lane & 3;
    int m0 = (w >> 2) * 64;
    int j0 = (w & 3) * 32;

    float dacc[4][4][4];
#pragma unroll
    for (int mi = 0; mi < 4; mi++)
#pragma unroll
        for (int nj = 0; nj < 4; nj++)
#pragma unroll
            for (int r = 0; r < 4; r++) dacc[mi][nj][r] = 0.0f;

    const float*  qb   = q   + (size_t)b * BSTRIDE + h * DDIM;
    const float*  kb   = kin + (size_t)b * BSTRIDE + h * DDIM;
    const __half* ktb  = g_KtH + (size_t)bh * (64 * 128 * 64);
    const float*  keob = g_KEO + (size_t)bh * (64 * 128 * 2);

    int mI[2], k8I[2];
#pragma unroll
    for (int p = 0; p < 2; p++) { int idx = tid + p * 256; mI[p] = idx >> 2; k8I[p] = (idx & 3) * 8; }

    float4 ar[2][2];
    float4 br[2][2];
    float2 eor[2];
    uint4  brh[2];

    // prologue: tile 0
    {
        int l = kc * 16, dst = 0;
#pragma unroll
        for (int p = 0; p < 2; p++) {
            const float* s = qb + (size_t)(mI[p] * LSEG + l) * ROWSTRIDE + dst + k8I[p];
            ar[p][0] = *(const float4*)s;
            ar[p][1] = *(const float4*)(s + 4);
        }
        if (jh == 0) {
#pragma unroll
            for (int p = 0; p < 2; p++) {
                const float* s = kb + (size_t)(mI[p] * LSEG + l) * ROWSTRIDE + dst + k8I[p];
                br[p][0] = *(const float4*)s;
                br[p][1] = *(const float4*)(s + 4);
                eor[p]   = *(const float2*)(keob + ((size_t)l * 128 + mI[p]) * 2);
            }
        } else {
#pragma unroll
            for (int p = 0; p < 2; p++)
                brh[p] = *(const uint4*)(ktb + ((size_t)l * 128 + mI[p]) * 64 + dst + k8I[p]);
        }
    }

    for (int kt = 0; kt < 32; kt++) {
        __syncthreads();
        // STS (cvt fp32->fp16; re-transform folded on jh=0)
#pragma unroll
        for (int p = 0; p < 2; p++) {
            uint4 u;
            u.x = h2u(ar[p][0].x, ar[p][0].y);
            u.y = h2u(ar[p][0].z, ar[p][0].w);
            u.z = h2u(ar[p][1].x, ar[p][1].y);
            u.w = h2u(ar[p][1].z, ar[p][1].w);
            *(uint4*)&As[mI[p]][k8I[p]] = u;
        }
        if (jh == 0) {
#pragma unroll
            for (int p = 0; p < 2; p++) {
                float ex = (1.0f / 64.0f) * eor[p].x, ey = (1.0f / 64.0f) * eor[p].y;
                uint4 u;
                u.x = h2u(0.5f * br[p][0].x + ex, 0.5f * br[p][0].y + ey);
                u.y = h2u(0.5f * br[p][0].z + ex, 0.5f * br[p][0].w + ey);
                u.z = h2u(0.5f * br[p][1].x + ex, 0.5f * br[p][1].y + ey);
                u.w = h2u(0.5f * br[p][1].z + ex, 0.5f * br[p][1].w + ey);
                *(uint4*)&Bs[mI[p]][k8I[p]] = u;
            }
        } else {
#pragma unroll
            for (int p = 0; p < 2; p++)
                *(uint4*)&Bs[mI[p]][k8I[p]] = brh[p];
        }
        __syncthreads();

        // prefetch next tile into regs
        if (kt + 1 < 32) {
            int l   = kc * 16 + ((kt + 1) >> 1);
            int dst = ((kt + 1) & 1) * 32;
#pragma unroll
            for (int p = 0; p < 2; p++) {
                const float* s = qb + (size_t)(mI[p] * LSEG + l) * ROWSTRIDE + dst + k8I[p];
                ar[p][0] = *(const float4*)s;
                ar[p][1] = *(const float4*)(s + 4);
            }
            if (jh == 0) {
#pragma unroll
                for (int p = 0; p < 2; p++) {
                    const float* s = kb + (size_t)(mI[p] * LSEG + l) * ROWSTRIDE + dst + k8I[p];
                    br[p][0] = *(const float4*)s;
                    br[p][1] = *(const float4*)(s + 4);
                    eor[p]   = *(const float2*)(keob + ((size_t)l * 128 + mI[p]) * 2);
                }
            } else {
#pragma unroll
                for (int p = 0; p < 2; p++)
                    brh[p] = *(const uint4*)(ktb + ((size_t)l * 128 + mI[p]) * 64 + dst + k8I[p]);
            }
        }

        // MMA over smem tile: 2 k16 steps
#pragma unroll
        for (int s = 0; s < 2; s++) {
            int kb16 = s * 16;
            unsigned bb[4][2];
#pragma unroll
            for (int nj = 0; nj < 4; nj++) {
                int c = j0 + nj * 8 + g;
                bb[nj][0] = *(const unsigned*)&Bs[c][kb16 + 2 * t];
                bb[nj][1] = *(const unsigned*)&Bs[c][kb16 + 2 * t + 8];
            }
#pragma unroll
            for (int mi = 0; mi < 4; mi++) {
                int r = m0 + mi * 16 + g;
                unsigned a[4];
                a[0] = *(const unsigned*)&As[r][kb16 + 2 * t];
                a[1] = *(const unsigned*)&As[r + 8][kb16 + 2 * t];
                a[2] = *(const unsigned*)&As[r][kb16 + 2 * t + 8];
                a[3] = *(const unsigned*)&As[r + 8][kb16 + 2 * t + 8];
#pragma unroll
                for (int nj = 0; nj < 4; nj++) mma_f16(dacc[mi][nj], a, bb[nj]);
            }
        }
    }

    float* cp = g_Cpart + ((size_t)(kc * BH + bh) * MSEG) * 256 + (size_t)jh * 128;
#pragma unroll
    for (int mi = 0; mi < 4; mi++) {
#pragma unroll
        for (int nj = 0; nj < 4; nj++) {
            int r = m0 + mi * 16 + g;
            int c = j0 + nj * 8 + 2 * t;
            *(float2*)(cp + (size_t)r * 256 + c)       = make_float2(dacc[mi][nj][0], dacc[mi][nj][1]);
            *(float2*)(cp + (size_t)(r + 8) * 256 + c) = make_float2(dacc[mi][nj][2], dacc[mi][nj][3]);
        }
    }
}

// ---------------------------------------------------------------------------
// Kernel 3: reduce partials, |S|/512, row softmax -> g_A
// ---------------------------------------------------------------------------
__global__ __launch_bounds__(256) void softmax_k() {
    int bh   = blockIdx.x;
    int m    = blockIdx.y * 8 + (threadIdx.x >> 5);
    int lane = threadIdx.x & 31;

    float t[4];
#pragma unroll
    for (int u = 0; u < 4; u++) {
        int n = lane + u * 32;
        float sre = 0.0f, sim = 0.0f;
#pragma unroll
        for (int p = 0; p < KCH; p++) {
            const float* cp = g_Cpart + (((size_t)p * BH + bh) * MSEG + m) * 256;
            sre += cp[n];
            sim += cp[n + 128];
        }
        t[u] = sqrtf(sre * sre + sim * sim) * (1.0f / 512.0f);
    }
    float mx = fmaxf(fmaxf(t[0], t[1]), fmaxf(t[2], t[3]));
#pragma unroll
    for (int o = 16; o; o >>= 1) mx = fmaxf(mx, __shfl_xor_sync(0xffffffffu, mx, o));
    float e[4], s = 0.0f;
#pragma unroll
    for (int u = 0; u < 4; u++) { e[u] = expf(t[u] - mx); s += e[u]; }
#pragma unroll
    for (int o = 16; o; o >>= 1) s += __shfl_xor_sync(0xffffffffu, s, o);
    float inv = 1.0f / s;
    float* arow = g_A + ((size_t)bh * MSEG + m) * MSEG;
#pragma unroll
    for (int u = 0; u < 4; u++) arow[lane + u * 32] = e[u] * inv;
}

// ---------------------------------------------------------------------------
// Kernel 4: out = A @ v via FP16 mma.sync, reg pipelined.
// grid 4096 = bh*64 + l, block 256 (8 warps), tile 128m x 64d, 4 n-chunks of 32.
// v pre-paired into half2[kpair][d] so B-fragments are single 32-bit LDS.
// ---------------------------------------------------------------------------
__global__ __launch_bounds__(256, 2) void v_gemm_h(const float* __restrict__ v,
                                                   float* __restrict__ out) {
    __shared__ __align__(16) __half As[128][40];      // A chunk [m][n32]
    __shared__ __align__(16) __half2 vsp[16][72];     // v pairs [npair][d]

    int bx = blockIdx.x;
    int l  = bx & 63;
    int bh = bx >> 6;
    int b  = bh >> 4, h = bh & 15;
    int tid  = threadIdx.x;
    int lane = tid & 31;
    int w    = tid >> 5;
    int g = lane >> 2, t = lane & 3;
    int m0 = (w >> 1) * 32;
    int d0 = (w & 1) * 32;

    float dacc[2][4][4];
#pragma unroll
    for (int mi = 0; mi < 2; mi++)
#pragma unroll
        for (int dj = 0; dj < 4; dj++)
#pragma unroll
            for (int r = 0; r < 4; r++) dacc[mi][dj][r] = 0.0f;

    const float* vbase = v + (size_t)b * BSTRIDE + (size_t)l * ROWSTRIDE + h * DDIM;
    const float* Abase = g_A + (size_t)bh * MSEG * MSEG;

    int mI[2], k8I[2];
#pragma unroll
    for (int p = 0; p < 2; p++) { int idx = tid + p * 256; mI[p] = idx >> 2; k8I[p] = (idx & 3) * 8; }
    int kpV = tid >> 4;      // 0..15 pair index
    int d4V = tid & 15;      // 0..15, 4 d each

    float4 ar[2][2];
    float4 vr0, vr1;

    // prologue: chunk 0
#pragma unroll
    for (int p = 0; p < 2; p++) {
        const float* s = Abase + (size_t)mI[p] * MSEG + k8I[p];
        ar[p][0] = *(const float4*)s;
        ar[p][1] = *(const float4*)(s + 4);
    }
    vr0 = *(const float4*)(vbase + (size_t)(2 * kpV) * SEGSTRIDE + d4V * 4);
    vr1 = *(const float4*)(vbase + (size_t)(2 * kpV + 1) * SEGSTRIDE + d4V * 4);

    for (int nc = 0; nc < 4; nc++) {
        __syncthreads();
#pragma unroll
        for (int p = 0; p < 2; p++) {
            uint4 u;
            u.x = h2u(ar[p][0].x, ar[p][0].y);
            u.y = h2u(ar[p][0].z, ar[p][0].w);
            u.z = h2u(ar[p][1].x, ar[p][1].y);
            u.w = h2u(ar[p][1].z, ar[p][1].w);
            *(uint4*)&As[mI[p]][k8I[p]] = u;
        }
        {
            uint4 u;
            u.x = h2u(vr0.x, vr1.x);
            u.y = h2u(vr0.y, vr1.y);
            u.z = h2u(vr0.z, vr1.z);
            u.w = h2u(vr0.w, vr1.w);
            *(uint4*)&vsp[kpV][d4V * 4] = u;
        }
        __syncthreads();

        if (nc + 1 < 4) {
            int n0n = (nc + 1) * 32;
#pragma unroll
            for (int p = 0; p < 2; p++) {
                const float* s = Abase + (size_t)mI[p] * MSEG + n0n + k8I[p];
                ar[p][0] = *(const float4*)s;
                ar[p][1] = *(const float4*)(s + 4);
            }
            vr0 = *(const float4*)(vbase + (size_t)(n0n + 2 * kpV) * SEGSTRIDE + d4V * 4);
            vr1 = *(const float4*)(vbase + (size_t)(n0n + 2 * kpV + 1) * SEGSTRIDE + d4V * 4);
        }

#pragma unroll
        for (int s = 0; s < 2; s++) {
            int kb16 = s * 16;
            unsigned bb[4][2];
#pragma unroll
            for (int dj = 0; dj < 4; dj++) {
                int c = d0 + dj * 8 + g;
                bb[dj][0] = *(const unsigned*)&vsp[s * 8 + t][c];
                bb[dj][1] = *(const unsigned*)&vsp[s * 8 + t + 4][c];
            }
#pragma unroll
            for (int mi = 0; mi < 2; mi++) {
                int r = m0 + mi * 16 + g;
                unsigned a[4];
                a[0] = *(const unsigned*)&As[r][kb16 + 2 * t];
                a[1] = *(const unsigned*)&As[r + 8][kb16 + 2 * t];
                a[2] = *(const unsigned*)&As[r][kb16 + 2 * t + 8];
                a[3] = *(const unsigned*)&As[r + 8][kb16 + 2 * t + 8];
#pragma unroll
                for (int dj = 0; dj < 4; dj++) mma_f16(dacc[mi][dj], a, bb[dj]);
            }
        }
    }

    float* obase = out + (size_t)b * BSTRIDE + (size_t)l * ROWSTRIDE + h * DDIM;
#pragma unroll
    for (int mi = 0; mi < 2; mi++) {
#pragma unroll
        for (int dj = 0; dj < 4; dj++) {
            int r = m0 + mi * 16 + g;
            int c = d0 + dj * 8 + 2 * t;
            *(float2*)(obase + (size_t)r * SEGSTRIDE + c)       = make_float2(dacc[mi][dj][0], dacc[mi][dj][1]);
            *(float2*)(obase + (size_t)(r + 8) * SEGSTRIDE + c) = make_float2(dacc[mi][dj][2], dacc[mi][dj][3]);
        }
    }
}

// ---------------------------------------------------------------------------
extern "C" void kernel_launch(void* const* d_in, const int* in_sizes, int n_in,
                              void* d_out, int out_size) {
    const float* q = (const float*)d_in[0];
    const float* k = (const float*)d_in[1];
    const float* v = (const float*)d_in[2];
    float* out = (float*)d_out;

    build_ktim<<<BH * LSEG, 256>>>(k);
    gemm_scores_h<<<dim3(KCH, 2, BH), 256>>>(q, k);
    softmax_k<<<dim3(BH, 16), 256>>>();
    v_gemm_h<<<BH * LSEG, 256>>>(v, out);
}

// round 7
// speedup vs baseline: 3.3157x; 1.1740x over previous
#include <cuda_runtime.h>
#include <cuda_fp16.h>
#include <math.h>
#include <stdint.h>

// FourierAttention R7: FFT-free + FP16 mma.sync; merged scores kernel (N=256),
// v_gemm with A-resident SMEM + 8 l per CTA + double-buffered v.
// B=4, L=8192, H=16, D=64, Ls=64, M=128.

#define BDIM 4
#define LDIM 8192
#define HDIM 16
#define DDIM 64
#define LSEG 64
#define MSEG 128
#define BH   64
#define KDIM 4096
#define KCH  2
#define LPB  8
#define ROWSTRIDE 1024
#define SEGSTRIDE 65536
#define BSTRIDE (LDIM*ROWSTRIDE)

// Scratch (device globals: allocation-free, graph-capture safe)
__device__ __half g_KtH[(size_t)BH * LSEG * MSEG * DDIM]; // im-K, [bh][l][n][d], half
__device__ float g_KEO[(size_t)BH * LSEG * MSEG * 2];     // parity sums, [bh][l][n][2]
__device__ float g_Cpart[(size_t)KCH * BH * MSEG * 256];  // score partials
__device__ float g_A[(size_t)BH * MSEG * MSEG];           // softmax result

__device__ __forceinline__ void mma_f16(float* d, const unsigned* a, const unsigned* b) {
    asm volatile(
        "mma.sync.aligned.m16n8k16.row.col.f32.f16.f16.f32 "
        "{%0,%1,%2,%3},{%4,%5,%6,%7},{%8,%9},{%0,%1,%2,%3};"
        : "+f"(d[0]), "+f"(d[1]), "+f"(d[2]), "+f"(d[3])
        : "r"(a[0]), "r"(a[1]), "r"(a[2]), "r"(a[3]), "r"(b[0]), "r"(b[1]));
}

__device__ __forceinline__ unsigned h2u(float a, float b) {
    __half2 h = __floats2half2_rn(a, b);
    return *(unsigned*)&h;
}

// ---------------------------------------------------------------------------
// Kernel 1: Kt_im[bh][l][n][d] (half) + parity sums KEO (float)
// ---------------------------------------------------------------------------
__global__ __launch_bounds__(256) void build_ktim(const float* __restrict__ k) {
    __shared__ float sbuf[8704];
    __shared__ float ct[128];
    float (*ks)[129] = (float(*)[129])sbuf;

    int bx = blockIdx.x;
    int l  = bx & 63;
    int bh = bx >> 6;
    int b  = bh >> 4, h = bh & 15;
    int tid = threadIdx.x;

    const float* kbase = k + (size_t)b * BSTRIDE + (size_t)l * ROWSTRIDE + h * DDIM;

#pragma unroll
    for (int i = 0; i < 8; i++) {
        int idx = tid + i * 256;
        int n = idx >> 4, dq = idx & 15;
        float4 v = *(const float4*)(kbase + (size_t)n * SEGSTRIDE + dq * 4);
        ks[dq * 4 + 0][n] = v.x;
        ks[dq * 4 + 1][n] = v.y;
        ks[dq * 4 + 2][n] = v.z;
        ks[dq * 4 + 3][n] = v.w;
    }
    if (tid < 128) {
        int delta = tid - 64;
        float val = 0.0f;
        if (delta & 1) {
            float x = (float)delta * (1.0f / 64.0f);
            val = -(cospif(x) / sinpif(x)) * (1.0f / 64.0f);
        }
        ct[tid] = val;
    }
    __syncthreads();

    int n = tid & 127;
    int qp = tid >> 7;
    {
        float s = 0.0f;
#pragma unroll
        for (int t = 0; t < 32; t++) s += ks[2 * t + qp][n];
        g_KEO[(((size_t)bh * 64 + l) * 128 + n) * 2 + qp] = s;
    }
    float ctr[63];
#pragma unroll
    for (int u = 0; u < 63; u++) ctr[u] = ct[2 * u + 2 * qp + 1];
    float acc[32];
#pragma unroll
    for (int dd = 0; dd < 32; dd++) acc[dd] = 0.0f;
#pragma unroll
    for (int t = 0; t < 32; t++) {
        float kv = ks[(1 - qp) + 2 * t][n];
#pragma unroll
        for (int dd = 0; dd < 32; dd++) acc[dd] += ctr[dd - t + 31] * kv;
    }
    __syncthreads();
    float (*kts)[68] = (float(*)[68])sbuf;
#pragma unroll
    for (int dd = 0; dd < 32; dd++) kts[n][qp + 2 * dd] = acc[dd];
    __syncthreads();

    __half* base = g_KtH + ((size_t)bh * 64 + l) * (128 * 64);
#pragma unroll
    for (int i = 0; i < 4; i++) {
        int idx = tid + i * 256;
        int n2 = idx >> 3, q8 = idx & 7;
        const float* src = &kts[n2][q8 * 8];
        uint4 u;
        u.x = h2u(src[0], src[1]);
        u.y = h2u(src[2], src[3]);
        u.z = h2u(src[4], src[5]);
        u.w = h2u(src[6], src[7]);
        *(uint4*)(base + (size_t)n2 * 64 + q8 * 8) = u;
    }
}

// ---------------------------------------------------------------------------
// Kernel 2: merged scores GEMM (re+im in one pass), FP16 mma, reg prefetch.
// grid (KCH=2, bh=64), block 512 (16 warps), tile 128m x 256j, ktile 32.
// Bs rows [0,128): re = 0.5*K + KEO/64 (fp32 transform at STS); [128,256): KtH.
// ---------------------------------------------------------------------------
__global__ __launch_bounds__(512, 1) void gemm_scores_h2(const float* __restrict__ q,
                                                         const float* __restrict__ kin) {
    __shared__ __align__(16) __half As[128][40];
    __shared__ __align__(16) __half Bs[256][40];

    int kc = blockIdx.x;   // 0..1
    int bh = blockIdx.y;
    int b  = bh >> 4, h = bh & 15;
    int tid  = threadIdx.x;
    int lane = tid & 31;
    int w    = tid >> 5;
    int g = lane >> 2, t = lane & 3;
    int m0 = (w >> 2) * 32;
    int j0 = (w & 3) * 64;

    float dacc[2][8][4];
#pragma unroll
    for (int mi = 0; mi < 2; mi++)
#pragma unroll
        for (int nj = 0; nj < 8; nj++)
#pragma unroll
            for (int r = 0; r < 4; r++) dacc[mi][nj][r] = 0.0f;

    const float*  qb   = q   + (size_t)b * BSTRIDE + h * DDIM;
    const float*  kb   = kin + (size_t)b * BSTRIDE + h * DDIM;
    const __half* ktb  = g_KtH + (size_t)bh * (64 * 128 * 64);
    const float*  keob = g_KEO + (size_t)bh * (64 * 128 * 2);

    int mI  = tid >> 2;          // 0..127
    int k8I = (tid & 3) * 8;     // 0,8,16,24

    float4 ar0, ar1, br0, br1;
    float2 eor;
    uint4  brh;

    // prologue: tile kt=0
    {
        int l = kc * 32, dst = 0;
        const float* sq = qb + (size_t)(mI * LSEG + l) * ROWSTRIDE + dst + k8I;
        ar0 = *(const float4*)sq;
        ar1 = *(const float4*)(sq + 4);
        const float* sk = kb + (size_t)(mI * LSEG + l) * ROWSTRIDE + dst + k8I;
        br0 = *(const float4*)sk;
        br1 = *(const float4*)(sk + 4);
        eor = *(const float2*)(keob + ((size_t)l * 128 + mI) * 2);
        brh = *(const uint4*)(ktb + ((size_t)l * 128 + mI) * 64 + dst + k8I);
    }

    for (int kt = 0; kt < 64; kt++) {
        __syncthreads();
        // STS
        {
            uint4 u;
            u.x = h2u(ar0.x, ar0.y);
            u.y = h2u(ar0.z, ar0.w);
            u.z = h2u(ar1.x, ar1.y);
            u.w = h2u(ar1.z, ar1.w);
            *(uint4*)&As[mI][k8I] = u;
            float ex = (1.0f / 64.0f) * eor.x, ey = (1.0f / 64.0f) * eor.y;
            uint4 v;
            v.x = h2u(0.5f * br0.x + ex, 0.5f * br0.y + ey);
            v.y = h2u(0.5f * br0.z + ex, 0.5f * br0.w + ey);
            v.z = h2u(0.5f * br1.x + ex, 0.5f * br1.y + ey);
            v.w = h2u(0.5f * br1.z + ex, 0.5f * br1.w + ey);
            *(uint4*)&Bs[mI][k8I] = v;
            *(uint4*)&Bs[128 + mI][k8I] = brh;
        }
        __syncthreads();

        // prefetch next tile
        if (kt + 1 < 64) {
            int kap = kc * 2048 + (kt + 1) * 32;
            int l   = kap >> 6;
            int dst = kap & 63;
            const float* sq = qb + (size_t)(mI * LSEG + l) * ROWSTRIDE + dst + k8I;
            ar0 = *(const float4*)sq;
            ar1 = *(const float4*)(sq + 4);
            const float* sk = kb + (size_t)(mI * LSEG + l) * ROWSTRIDE + dst + k8I;
            br0 = *(const float4*)sk;
            br1 = *(const float4*)(sk + 4);
            eor = *(const float2*)(keob + ((size_t)l * 128 + mI) * 2);
            brh = *(const uint4*)(ktb + ((size_t)l * 128 + mI) * 64 + dst + k8I);
        }

        // MMA over smem tile: 2 k16 steps
#pragma unroll
        for (int s = 0; s < 2; s++) {
            int kb16 = s * 16;
            unsigned bb[8][2];
#pragma unroll
            for (int nj = 0; nj < 8; nj++) {
                int c = j0 + nj * 8 + g;
                bb[nj][0] = *(const unsigned*)&Bs[c][kb16 + 2 * t];
                bb[nj][1] = *(const unsigned*)&Bs[c][kb16 + 2 * t + 8];
            }
#pragma unroll
            for (int mi = 0; mi < 2; mi++) {
                int r = m0 + mi * 16 + g;
                unsigned a[4];
                a[0] = *(const unsigned*)&As[r][kb16 + 2 * t];
                a[1] = *(const unsigned*)&As[r + 8][kb16 + 2 * t];
                a[2] = *(const unsigned*)&As[r][kb16 + 2 * t + 8];
                a[3] = *(const unsigned*)&As[r + 8][kb16 + 2 * t + 8];
#pragma unroll
                for (int nj = 0; nj < 8; nj++) mma_f16(dacc[mi][nj], a, bb[nj]);
            }
        }
    }

    float* cp = g_Cpart + ((size_t)(kc * BH + bh) * MSEG) * 256;
#pragma unroll
    for (int mi = 0; mi < 2; mi++) {
#pragma unroll
        for (int nj = 0; nj < 8; nj++) {
            int r = m0 + mi * 16 + g;
            int c = j0 + nj * 8 + 2 * t;
            *(float2*)(cp + (size_t)r * 256 + c)       = make_float2(dacc[mi][nj][0], dacc[mi][nj][1]);
            *(float2*)(cp + (size_t)(r + 8) * 256 + c) = make_float2(dacc[mi][nj][2], dacc[mi][nj][3]);
        }
    }
}

// ---------------------------------------------------------------------------
// Kernel 3: reduce partials, |S|/512, row softmax -> g_A
// ---------------------------------------------------------------------------
__global__ __launch_bounds__(256) void softmax_k() {
    int bh   = blockIdx.x;
    int m    = blockIdx.y * 8 + (threadIdx.x >> 5);
    int lane = threadIdx.x & 31;

    float t[4];
#pragma unroll
    for (int u = 0; u < 4; u++) {
        int n = lane + u * 32;
        float sre = 0.0f, sim = 0.0f;
#pragma unroll
        for (int p = 0; p < KCH; p++) {
            const float* cp = g_Cpart + (((size_t)p * BH + bh) * MSEG + m) * 256;
            sre += cp[n];
            sim += cp[n + 128];
        }
        t[u] = sqrtf(sre * sre + sim * sim) * (1.0f / 512.0f);
    }
    float mx = fmaxf(fmaxf(t[0], t[1]), fmaxf(t[2], t[3]));
#pragma unroll
    for (int o = 16; o; o >>= 1) mx = fmaxf(mx, __shfl_xor_sync(0xffffffffu, mx, o));
    float e[4], s = 0.0f;
#pragma unroll
    for (int u = 0; u < 4; u++) { e[u] = expf(t[u] - mx); s += e[u]; }
#pragma unroll
    for (int o = 16; o; o >>= 1) s += __shfl_xor_sync(0xffffffffu, s, o);
    float inv = 1.0f / s;
    float* arow = g_A + ((size_t)bh * MSEG + m) * MSEG;
#pragma unroll
    for (int u = 0; u < 4; u++) arow[lane + u * 32] = e[u] * inv;
}

// ---------------------------------------------------------------------------
// Kernel 4: out = A @ v, FP16 mma. A resident in SMEM (fp16), 8 l per CTA,
// v double-buffered. grid (bh*8), block 256 (8 warps), warp tile 32m x 32d.
// ---------------------------------------------------------------------------
__global__ __launch_bounds__(256, 2) void v_gemm_h2(const float* __restrict__ v,
                                                    float* __restrict__ out) {
    extern __shared__ char dynsm[];
    __half (*As)[136]   = (__half(*)[136])dynsm;                       // 128 x 136 half
    __half2 (*vsp)[72]  = (__half2(*)[72])(dynsm + 128 * 136 * 2);     // 2*64 x 72 half2

    int bx = blockIdx.x;
    int lg = bx & 7;
    int bh = bx >> 3;
    int b  = bh >> 4, h = bh & 15;
    int tid  = threadIdx.x;
    int lane = tid & 31;
    int w    = tid >> 5;
    int g = lane >> 2, t = lane & 3;
    int m0 = (w >> 1) * 32;
    int d0 = (w & 1) * 32;

    const float* Abase = g_A + (size_t)bh * MSEG * MSEG;
    const float* vbh   = v + (size_t)b * BSTRIDE + h * DDIM;
    float* obh         = out + (size_t)b * BSTRIDE + h * DDIM;

    // load A once, fp32 -> fp16
#pragma unroll
    for (int i = 0; i < 16; i++) {
        int idx = tid + i * 256;      // 0..4095
        int m = idx >> 5, qc = idx & 31;
        float4 av = *(const float4*)(Abase + (size_t)m * MSEG + qc * 4);
        uint2 u;
        u.x = h2u(av.x, av.y);
        u.y = h2u(av.z, av.w);
        *(uint2*)&As[m][qc * 4] = u;
    }

    int kpV = tid >> 4;   // 0..15
    int d4V = tid & 15;   // 0..15

    float4 pv[8];
    {
        const float* vb = vbh + (size_t)(lg * LPB) * ROWSTRIDE;
#pragma unroll
        for (int i = 0; i < 4; i++) {
            int kp = kpV + 16 * i;
            pv[2 * i]     = *(const float4*)(vb + (size_t)(2 * kp) * SEGSTRIDE + d4V * 4);
            pv[2 * i + 1] = *(const float4*)(vb + (size_t)(2 * kp + 1) * SEGSTRIDE + d4V * 4);
        }
    }

    for (int il = 0; il < LPB; il++) {
        int l   = lg * LPB + il;
        int buf = (il & 1) * 64;
        __syncthreads();   // prior MMA on this buffer done
#pragma unroll
        for (int i = 0; i < 4; i++) {
            int kp = kpV + 16 * i;
            uint4 u;
            u.x = h2u(pv[2 * i].x, pv[2 * i + 1].x);
            u.y = h2u(pv[2 * i].y, pv[2 * i + 1].y);
            u.z = h2u(pv[2 * i].z, pv[2 * i + 1].z);
            u.w = h2u(pv[2 * i].w, pv[2 * i + 1].w);
            *(uint4*)&vsp[buf + kp][d4V * 4] = u;
        }
        __syncthreads();

        if (il + 1 < LPB) {
            const float* vb = vbh + (size_t)(l + 1) * ROWSTRIDE;
#pragma unroll
            for (int i = 0; i < 4; i++) {
                int kp = kpV + 16 * i;
                pv[2 * i]     = *(const float4*)(vb + (size_t)(2 * kp) * SEGSTRIDE + d4V * 4);
                pv[2 * i + 1] = *(const float4*)(vb + (size_t)(2 * kp + 1) * SEGSTRIDE + d4V * 4);
            }
        }

        float dacc[2][4][4];
#pragma unroll
        for (int mi = 0; mi < 2; mi++)
#pragma unroll
            for (int dj = 0; dj < 4; dj++)
#pragma unroll
                for (int r = 0; r < 4; r++) dacc[mi][dj][r] = 0.0f;

#pragma unroll
        for (int s = 0; s < 8; s++) {
            int kb16 = s * 16;
            unsigned bb[4][2];
#pragma unroll
            for (int dj = 0; dj < 4; dj++) {
                int c = d0 + dj * 8 + g;
                bb[dj][0] = *(const unsigned*)&vsp[buf + s * 8 + t][c];
                bb[dj][1] = *(const unsigned*)&vsp[buf + s * 8 + t + 4][c];
            }
#pragma unroll
            for (int mi = 0; mi < 2; mi++) {
                int r = m0 + mi * 16 + g;
                unsigned a[4];
                a[0] = *(const unsigned*)&As[r][kb16 + 2 * t];
                a[1] = *(const unsigned*)&As[r + 8][kb16 + 2 * t];
                a[2] = *(const unsigned*)&As[r][kb16 + 2 * t + 8];
                a[3] = *(const unsigned*)&As[r + 8][kb16 + 2 * t + 8];
#pragma unroll
                for (int dj = 0; dj < 4; dj++) mma_f16(dacc[mi][dj], a, bb[dj]);
            }
        }

        float* obase = obh + (size_t)l * ROWSTRIDE;
#pragma unroll
        for (int mi = 0; mi < 2; mi++) {
#pragma unroll
            for (int dj = 0; dj < 4; dj++) {
                int r = m0 + mi * 16 + g;
                int c = d0 + dj * 8 + 2 * t;
                *(float2*)(obase + (size_t)r * SEGSTRIDE + c)       = make_float2(dacc[mi][dj][0], dacc[mi][dj][1]);
                *(float2*)(obase + (size_t)(r + 8) * SEGSTRIDE + c) = make_float2(dacc[mi][dj][2], dacc[mi][dj][3]);
            }
        }
    }
}

#define VG_SMEM (128 * 136 * 2 + 2 * 64 * 72 * 4)

// ---------------------------------------------------------------------------
extern "C" void kernel_launch(void* const* d_in, const int* in_sizes, int n_in,
                              void* d_out, int out_size) {
    const float* q = (const float*)d_in[0];
    const float* k = (const float*)d_in[1];
    const float* v = (const float*)d_in[2];
    float* out = (float*)d_out;

    cudaFuncSetAttribute(v_gemm_h2, cudaFuncAttributeMaxDynamicSharedMemorySize, VG_SMEM);

    build_ktim<<<BH * LSEG, 256>>>(k);
    gemm_scores_h2<<<dim3(KCH, BH), 512>>>(q, k);
    softmax_k<<<dim3(BH, 16), 256>>>();
    v_gemm_h2<<<BH * LPB, 256, VG_SMEM>>>(v, out);
}

// round 8
// speedup vs baseline: 3.6896x; 1.1128x over previous
#include <cuda_runtime.h>
#include <cuda_fp16.h>
#include <math.h>
#include <stdint.h>

// FourierAttention R8: FP16 mma.sync + ldmatrix + single-sync double-buffered
// pipelines; softmax emits fp16 A. B=4, L=8192, H=16, D=64, Ls=64, M=128.

#define BDIM 4
#define LDIM 8192
#define HDIM 16
#define DDIM 64
#define LSEG 64
#define MSEG 128
#define BH   64
#define KDIM 4096
#define KCH  2
#define LPB  8
#define ROWSTRIDE 1024
#define SEGSTRIDE 65536
#define BSTRIDE (LDIM*ROWSTRIDE)

// Scratch (device globals: allocation-free, graph-capture safe)
__device__ __half g_KtH[(size_t)BH * LSEG * MSEG * DDIM]; // im-K, [bh][l][n][d], half
__device__ float g_KEO[(size_t)BH * LSEG * MSEG * 2];     // parity sums
__device__ float g_Cpart[(size_t)KCH * BH * MSEG * 256];  // score partials
__device__ __half g_Ah[(size_t)BH * MSEG * MSEG];         // softmax result (fp16)

__device__ __forceinline__ void mma_f16(float* d, const unsigned* a,
                                        unsigned b0, unsigned b1) {
    asm volatile(
        "mma.sync.aligned.m16n8k16.row.col.f32.f16.f16.f32 "
        "{%0,%1,%2,%3},{%4,%5,%6,%7},{%8,%9},{%0,%1,%2,%3};"
        : "+f"(d[0]), "+f"(d[1]), "+f"(d[2]), "+f"(d[3])
        : "r"(a[0]), "r"(a[1]), "r"(a[2]), "r"(a[3]), "r"(b0), "r"(b1));
}

__device__ __forceinline__ unsigned h2u(float a, float b) {
    __half2 h = __floats2half2_rn(a, b);
    return *(unsigned*)&h;
}

__device__ __forceinline__ uint32_t smem_u32(const void* p) {
    uint32_t a;
    asm("{ .reg .u64 t; cvta.to.shared.u64 t, %1; cvt.u32.u64 %0, t; }" : "=r"(a) : "l"(p));
    return a;
}

__device__ __forceinline__ void ldsm_x4(unsigned* r, uint32_t addr) {
    asm volatile("ldmatrix.sync.aligned.m8n8.x4.shared.b16 {%0,%1,%2,%3}, [%4];"
        : "=r"(r[0]), "=r"(r[1]), "=r"(r[2]), "=r"(r[3]) : "r"(addr));
}

// ---------------------------------------------------------------------------
// Kernel 1: Kt_im[bh][l][n][d] (half) + parity sums KEO (float)
// ---------------------------------------------------------------------------
__global__ __launch_bounds__(256) void build_ktim(const float* __restrict__ k) {
    __shared__ float sbuf[8704];
    __shared__ float ct[128];
    float (*ks)[129] = (float(*)[129])sbuf;

    int bx = blockIdx.x;
    int l  = bx & 63;
    int bh = bx >> 6;
    int b  = bh >> 4, h = bh & 15;
    int tid = threadIdx.x;

    const float* kbase = k + (size_t)b * BSTRIDE + (size_t)l * ROWSTRIDE + h * DDIM;

#pragma unroll
    for (int i = 0; i < 8; i++) {
        int idx = tid + i * 256;
        int n = idx >> 4, dq = idx & 15;
        float4 v = *(const float4*)(kbase + (size_t)n * SEGSTRIDE + dq * 4);
        ks[dq * 4 + 0][n] = v.x;
        ks[dq * 4 + 1][n] = v.y;
        ks[dq * 4 + 2][n] = v.z;
        ks[dq * 4 + 3][n] = v.w;
    }
    if (tid < 128) {
        int delta = tid - 64;
        float val = 0.0f;
        if (delta & 1) {
            float x = (float)delta * (1.0f / 64.0f);
            val = -(cospif(x) / sinpif(x)) * (1.0f / 64.0f);
        }
        ct[tid] = val;
    }
    __syncthreads();

    int n = tid & 127;
    int qp = tid >> 7;
    {
        float s = 0.0f;
#pragma unroll
        for (int t = 0; t < 32; t++) s += ks[2 * t + qp][n];
        g_KEO[(((size_t)bh * 64 + l) * 128 + n) * 2 + qp] = s;
    }
    float ctr[63];
#pragma unroll
    for (int u = 0; u < 63; u++) ctr[u] = ct[2 * u + 2 * qp + 1];
    float acc[32];
#pragma unroll
    for (int dd = 0; dd < 32; dd++) acc[dd] = 0.0f;
#pragma unroll
    for (int t = 0; t < 32; t++) {
        float kv = ks[(1 - qp) + 2 * t][n];
#pragma unroll
        for (int dd = 0; dd < 32; dd++) acc[dd] += ctr[dd - t + 31] * kv;
    }
    __syncthreads();
    float (*kts)[68] = (float(*)[68])sbuf;
#pragma unroll
    for (int dd = 0; dd < 32; dd++) kts[n][qp + 2 * dd] = acc[dd];
    __syncthreads();

    __half* base = g_KtH + ((size_t)bh * 64 + l) * (128 * 64);
#pragma unroll
    for (int i = 0; i < 4; i++) {
        int idx = tid + i * 256;
        int n2 = idx >> 3, q8 = idx & 7;
        const float* src = &kts[n2][q8 * 8];
        uint4 u;
        u.x = h2u(src[0], src[1]);
        u.y = h2u(src[2], src[3]);
        u.z = h2u(src[4], src[5]);
        u.w = h2u(src[6], src[7]);
        *(uint4*)(base + (size_t)n2 * 64 + q8 * 8) = u;
    }
}

// ---------------------------------------------------------------------------
// Kernel 2: merged scores GEMM, FP16 mma + ldmatrix, double-buffered smem,
// single sync per ktile. grid (KCH=2, bh=64), block 512, tile 128m x 256j.
// ---------------------------------------------------------------------------
#define A_HALVES (128 * 40)          // 5120 halves = 10240 B
#define BUF_HALVES (A_HALVES + 256 * 40)  // 15360 halves = 30720 B
#define SC_SMEM (2 * BUF_HALVES * 2)      // 61440 B

__global__ __launch_bounds__(512, 1) void gemm_scores_h3(const float* __restrict__ q,
                                                         const float* __restrict__ kin) {
    extern __shared__ __half dynh[];

    int kc = blockIdx.x;
    int bh = blockIdx.y;
    int b  = bh >> 4, h = bh & 15;
    int tid  = threadIdx.x;
    int lane = tid & 31;
    int w    = tid >> 5;
    int g = lane >> 2, t = lane & 3;
    int m0 = (w >> 2) * 32;
    int j0 = (w & 3) * 64;

    float dacc[2][8][4];
#pragma unroll
    for (int mi = 0; mi < 2; mi++)
#pragma unroll
        for (int nj = 0; nj < 8; nj++)
#pragma unroll
            for (int r = 0; r < 4; r++) dacc[mi][nj][r] = 0.0f;

    const float*  qb   = q   + (size_t)b * BSTRIDE + h * DDIM;
    const float*  kb   = kin + (size_t)b * BSTRIDE + h * DDIM;
    const __half* ktb  = g_KtH + (size_t)bh * (64 * 128 * 64);
    const float*  keob = g_KEO + (size_t)bh * (64 * 128 * 2);

    int mI  = tid >> 2;
    int k8I = (tid & 3) * 8;

    uint32_t sbase = smem_u32(dynh);
    // ldmatrix per-lane byte offsets within a buffer
    uint32_t offA[2], offB[4];
#pragma unroll
    for (int mi = 0; mi < 2; mi++) {
        int row = m0 + mi * 16 + (lane & 7) + ((lane >> 3) & 1) * 8;
        int col = ((lane >> 4) & 1) * 8;
        offA[mi] = (uint32_t)(row * 40 + col) * 2;
    }
#pragma unroll
    for (int njp = 0; njp < 4; njp++) {
        int row = j0 + njp * 16 + (lane & 7) + ((lane >> 4) & 1) * 8;
        int col = ((lane >> 3) & 1) * 8;
        offB[njp] = (uint32_t)(A_HALVES + row * 40 + col) * 2;
    }
    uint32_t stsA  = (uint32_t)(mI * 40 + k8I);
    uint32_t stsBr = (uint32_t)(A_HALVES + mI * 40 + k8I);
    uint32_t stsBi = (uint32_t)(A_HALVES + (128 + mI) * 40 + k8I);

    float4 ar0, ar1, br0, br1;
    float2 eor;
    uint4  brh;

    // prologue: tile kt=0
    {
        int l = kc * 32;
        const float* sq = qb + (size_t)(mI * LSEG + l) * ROWSTRIDE + k8I;
        ar0 = *(const float4*)sq;
        ar1 = *(const float4*)(sq + 4);
        const float* sk = kb + (size_t)(mI * LSEG + l) * ROWSTRIDE + k8I;
        br0 = *(const float4*)sk;
        br1 = *(const float4*)(sk + 4);
        eor = *(const float2*)(keob + ((size_t)l * 128 + mI) * 2);
        brh = *(const uint4*)(ktb + ((size_t)l * 128 + mI) * 64 + k8I);
    }

    for (int kt = 0; kt < 64; kt++) {
        int buf = kt & 1;
        __half* bp = dynh + buf * BUF_HALVES;
        // STS current tile into buf
        {
            uint4 u;
            u.x = h2u(ar0.x, ar0.y);
            u.y = h2u(ar0.z, ar0.w);
            u.z = h2u(ar1.x, ar1.y);
            u.w = h2u(ar1.z, ar1.w);
            *(uint4*)(bp + stsA) = u;
            float ex = (1.0f / 64.0f) * eor.x, ey = (1.0f / 64.0f) * eor.y;
            uint4 v;
            v.x = h2u(0.5f * br0.x + ex, 0.5f * br0.y + ey);
            v.y = h2u(0.5f * br0.z + ex, 0.5f * br0.w + ey);
            v.z = h2u(0.5f * br1.x + ex, 0.5f * br1.y + ey);
            v.w = h2u(0.5f * br1.z + ex, 0.5f * br1.w + ey);
            *(uint4*)(bp + stsBr) = v;
            *(uint4*)(bp + stsBi) = brh;
        }
        // prefetch next tile
        if (kt + 1 < 64) {
            int kap = kc * 2048 + (kt + 1) * 32;
            int l   = kap >> 6;
            int dst = kap & 63;
            const float* sq = qb + (size_t)(mI * LSEG + l) * ROWSTRIDE + dst + k8I;
            ar0 = *(const float4*)sq;
            ar1 = *(const float4*)(sq + 4);
            const float* sk = kb + (size_t)(mI * LSEG + l) * ROWSTRIDE + dst + k8I;
            br0 = *(const float4*)sk;
            br1 = *(const float4*)(sk + 4);
            eor = *(const float2*)(keob + ((size_t)l * 128 + mI) * 2);
            brh = *(const uint4*)(ktb + ((size_t)l * 128 + mI) * 64 + dst + k8I);
        }
        __syncthreads();

        uint32_t bb0 = sbase + buf * (BUF_HALVES * 2);
#pragma unroll
        for (int s = 0; s < 2; s++) {
            uint32_t so = bb0 + s * 32;
            unsigned a[2][4];
#pragma unroll
            for (int mi = 0; mi < 2; mi++) ldsm_x4(a[mi], so + offA[mi]);
#pragma unroll
            for (int njp = 0; njp < 4; njp++) {
                unsigned bbv[4];
                ldsm_x4(bbv, so + offB[njp]);
#pragma unroll
                for (int mi = 0; mi < 2; mi++) {
                    mma_f16(dacc[mi][2 * njp],     a[mi], bbv[0], bbv[1]);
                    mma_f16(dacc[mi][2 * njp + 1], a[mi], bbv[2], bbv[3]);
                }
            }
        }
    }

    float* cp = g_Cpart + ((size_t)(kc * BH + bh) * MSEG) * 256;
#pragma unroll
    for (int mi = 0; mi < 2; mi++) {
#pragma unroll
        for (int nj = 0; nj < 8; nj++) {
            int r = m0 + mi * 16 + g;
            int c = j0 + nj * 8 + 2 * t;
            *(float2*)(cp + (size_t)r * 256 + c)       = make_float2(dacc[mi][nj][0], dacc[mi][nj][1]);
            *(float2*)(cp + (size_t)(r + 8) * 256 + c) = make_float2(dacc[mi][nj][2], dacc[mi][nj][3]);
        }
    }
}

// ---------------------------------------------------------------------------
// Kernel 3: reduce partials, |S|/512, row softmax -> g_Ah (fp16)
// ---------------------------------------------------------------------------
__global__ __launch_bounds__(256) void softmax_k() {
    int bh   = blockIdx.x;
    int m    = blockIdx.y * 8 + (threadIdx.x >> 5);
    int lane = threadIdx.x & 31;

    float t[4];
#pragma unroll
    for (int u = 0; u < 4; u++) {
        int n = lane + u * 32;
        float sre = 0.0f, sim = 0.0f;
#pragma unroll
        for (int p = 0; p < KCH; p++) {
            const float* cp = g_Cpart + (((size_t)p * BH + bh) * MSEG + m) * 256;
            sre += cp[n];
            sim += cp[n + 128];
        }
        t[u] = sqrtf(sre * sre + sim * sim) * (1.0f / 512.0f);
    }
    float mx = fmaxf(fmaxf(t[0], t[1]), fmaxf(t[2], t[3]));
#pragma unroll
    for (int o = 16; o; o >>= 1) mx = fmaxf(mx, __shfl_xor_sync(0xffffffffu, mx, o));
    float e[4], s = 0.0f;
#pragma unroll
    for (int u = 0; u < 4; u++) { e[u] = expf(t[u] - mx); s += e[u]; }
#pragma unroll
    for (int o = 16; o; o >>= 1) s += __shfl_xor_sync(0xffffffffu, s, o);
    float inv = 1.0f / s;
    __half* arow = g_Ah + ((size_t)bh * MSEG + m) * MSEG;
#pragma unroll
    for (int u = 0; u < 4; u++) arow[lane + u * 32] = __float2half(e[u] * inv);
}

// ---------------------------------------------------------------------------
// Kernel 4: out = A @ v, FP16 mma. A resident (copied from g_Ah), 8 l per CTA,
// v double-buffered, single sync per l. grid (bh*8), block 256.
// ---------------------------------------------------------------------------
__global__ __launch_bounds__(256, 2) void v_gemm_h3(const float* __restrict__ v,
                                                    float* __restrict__ out) {
    extern __shared__ char dynsm[];
    __half (*As)[136]  = (__half(*)[136])dynsm;                      // 128 x 136 half
    __half2 (*vsp)[72] = (__half2(*)[72])(dynsm + 128 * 136 * 2);    // 2*64 x 72 half2

    int bx = blockIdx.x;
    int lg = bx & 7;
    int bh = bx >> 3;
    int b  = bh >> 4, h = bh & 15;
    int tid  = threadIdx.x;
    int lane = tid & 31;
    int w    = tid >> 5;
    int g = lane >> 2, t = lane & 3;
    int m0 = (w >> 1) * 32;
    int d0 = (w & 1) * 32;

    const __half* Abase = g_Ah + (size_t)bh * MSEG * MSEG;
    const float* vbh    = v + (size_t)b * BSTRIDE + h * DDIM;
    float* obh          = out + (size_t)b * BSTRIDE + h * DDIM;

    int kpV = tid >> 4;
    int d4V = tid & 15;

    // issue v LDGs for il=0 first (hide under A copy)
    float4 pv[8];
    {
        const float* vb = vbh + (size_t)(lg * LPB) * ROWSTRIDE;
#pragma unroll
        for (int i = 0; i < 4; i++) {
            int kp = kpV + 16 * i;
            pv[2 * i]     = *(const float4*)(vb + (size_t)(2 * kp) * SEGSTRIDE + d4V * 4);
            pv[2 * i + 1] = *(const float4*)(vb + (size_t)(2 * kp + 1) * SEGSTRIDE + d4V * 4);
        }
    }

    // copy A (fp16, raw uint4)
#pragma unroll
    for (int i = 0; i < 8; i++) {
        int idx = tid + i * 256;          // 0..2047
        int m = idx >> 4, c = idx & 15;
        uint4 u = *(const uint4*)(Abase + (size_t)m * MSEG + c * 8);
        *(uint4*)&As[m][c * 8] = u;
    }

    for (int il = 0; il < LPB; il++) {
        int l   = lg * LPB + il;
        int buf = (il & 1) * 64;
        // STS current v into buf
#pragma unroll
        for (int i = 0; i < 4; i++) {
            int kp = kpV + 16 * i;
            uint4 u;
            u.x = h2u(pv[2 * i].x, pv[2 * i + 1].x);
            u.y = h2u(pv[2 * i].y, pv[2 * i + 1].y);
            u.z = h2u(pv[2 * i].z, pv[2 * i + 1].z);
            u.w = h2u(pv[2 * i].w, pv[2 * i + 1].w);
            *(uint4*)&vsp[buf + kp][d4V * 4] = u;
        }
        // prefetch next l
        if (il + 1 < LPB) {
            const float* vb = vbh + (size_t)(l + 1) * ROWSTRIDE;
#pragma unroll
            for (int i = 0; i < 4; i++) {
                int kp = kpV + 16 * i;
                pv[2 * i]     = *(const float4*)(vb + (size_t)(2 * kp) * SEGSTRIDE + d4V * 4);
                pv[2 * i + 1] = *(const float4*)(vb + (size_t)(2 * kp + 1) * SEGSTRIDE + d4V * 4);
            }
        }
        __syncthreads();

        float dacc[2][4][4];
#pragma unroll
        for (int mi = 0; mi < 2; mi++)
#pragma unroll
            for (int dj = 0; dj < 4; dj++)
#pragma unroll
                for (int r = 0; r < 4; r++) dacc[mi][dj][r] = 0.0f;

#pragma unroll
        for (int s = 0; s < 8; s++) {
            int kb16 = s * 16;
            unsigned bb[4][2];
#pragma unroll
            for (int dj = 0; dj < 4; dj++) {
                int c = d0 + dj * 8 + g;
                bb[dj][0] = *(const unsigned*)&vsp[buf + s * 8 + t][c];
                bb[dj][1] = *(const unsigned*)&vsp[buf + s * 8 + t + 4][c];
            }
#pragma unroll
            for (int mi = 0; mi < 2; mi++) {
                int r = m0 + mi * 16 + g;
                unsigned a[4];
                a[0] = *(const unsigned*)&As[r][kb16 + 2 * t];
                a[1] = *(const unsigned*)&As[r + 8][kb16 + 2 * t];
                a[2] = *(const unsigned*)&As[r][kb16 + 2 * t + 8];
                a[3] = *(const unsigned*)&As[r + 8][kb16 + 2 * t + 8];
#pragma unroll
                for (int dj = 0; dj < 4; dj++) mma_f16(dacc[mi][dj], a, bb[dj][0], bb[dj][1]);
            }
        }

        float* obase = obh + (size_t)l * ROWSTRIDE;
#pragma unroll
        for (int mi = 0; mi < 2; mi++) {
#pragma unroll
            for (int dj = 0; dj < 4; dj++) {
                int r = m0 + mi * 16 + g;
                int c = d0 + dj * 8 + 2 * t;
                *(float2*)(obase + (size_t)r * SEGSTRIDE + c)       = make_float2(dacc[mi][dj][0], dacc[mi][dj][1]);
                *(float2*)(obase + (size_t)(r + 8) * SEGSTRIDE + c) = make_float2(dacc[mi][dj][2], dacc[mi][dj][3]);
            }
        }
    }
}

#define VG_SMEM (128 * 136 * 2 + 2 * 64 * 72 * 4)

// ---------------------------------------------------------------------------
extern "C" void kernel_launch(void* const* d_in, const int* in_sizes, int n_in,
                              void* d_out, int out_size) {
    const float* q = (const float*)d_in[0];
    const float* k = (const float*)d_in[1];
    const float* v = (const float*)d_in[2];
    float* out = (float*)d_out;

    cudaFuncSetAttribute(gemm_scores_h3, cudaFuncAttributeMaxDynamicSharedMemorySize, SC_SMEM);
    cudaFuncSetAttribute(v_gemm_h3, cudaFuncAttributeMaxDynamicSharedMemorySize, VG_SMEM);

    build_ktim<<<BH * LSEG, 256>>>(k);
    gemm_scores_h3<<<dim3(KCH, BH), 512, SC_SMEM>>>(q, k);
    softmax_k<<<dim3(BH, 16), 256>>>();
    v_gemm_h3<<<BH * LPB, 256, VG_SMEM>>>(v, out);
}

// round 9
// speedup vs baseline: 3.8784x; 1.0512x over previous
#include <cuda_runtime.h>
#include <cuda_fp16.h>
#include <math.h>
#include <stdint.h>

// FourierAttention R9: build kernel's cot-convolution moved to tensor cores
// (two 128x32x32 fp16 MMAs per (bh,l)); build emits FULL transformed Kt fp16
// (re|im), so scores reads only Q + Kt. B=4, L=8192, H=16, D=64, Ls=64, M=128.

#define BDIM 4
#define LDIM 8192
#define HDIM 16
#define DDIM 64
#define LSEG 64
#define MSEG 128
#define BH   64
#define KDIM 4096
#define KCH  2
#define LPB  8
#define ROWSTRIDE 1024
#define SEGSTRIDE 65536
#define BSTRIDE (LDIM*ROWSTRIDE)

// Scratch (device globals: allocation-free, graph-capture safe)
__device__ __half g_KtF[(size_t)BH * LSEG * MSEG * 128]; // Kt [bh][l][n][re0:64|im64:128]
__device__ float g_Cpart[(size_t)KCH * BH * MSEG * 256]; // score partials
__device__ __half g_Ah[(size_t)BH * MSEG * MSEG];        // softmax result (fp16)

__device__ __forceinline__ void mma_f16(float* d, const unsigned* a,
                                        unsigned b0, unsigned b1) {
    asm volatile(
        "mma.sync.aligned.m16n8k16.row.col.f32.f16.f16.f32 "
        "{%0,%1,%2,%3},{%4,%5,%6,%7},{%8,%9},{%0,%1,%2,%3};"
        : "+f"(d[0]), "+f"(d[1]), "+f"(d[2]), "+f"(d[3])
        : "r"(a[0]), "r"(a[1]), "r"(a[2]), "r"(a[3]), "r"(b0), "r"(b1));
}

__device__ __forceinline__ unsigned h2u(float a, float b) {
    __half2 h = __floats2half2_rn(a, b);
    return *(unsigned*)&h;
}

__device__ __forceinline__ uint32_t smem_u32(const void* p) {
    uint32_t a;
    asm("{ .reg .u64 t; cvta.to.shared.u64 t, %1; cvt.u32.u64 %0, t; }" : "=r"(a) : "l"(p));
    return a;
}

__device__ __forceinline__ void ldsm_x4(unsigned* r, uint32_t addr) {
    asm volatile("ldmatrix.sync.aligned.m8n8.x4.shared.b16 {%0,%1,%2,%3}, [%4];"
        : "=r"(r[0]), "=r"(r[1]), "=r"(r[2]), "=r"(r[3]) : "r"(addr));
}

// ---------------------------------------------------------------------------
// Kernel 1: build full Kt[bh][l][n][0:128] fp16.
//   re cols 0:64  = 0.5*k + parity_sum(k)/64   (FMA, trivial)
//   im cols 64:128 = parity-split cot correlation as two 128x32x32 fp16 MMAs
// grid 4096 = bh*64 + l, block 256 (8 warps, 16 n-rows each), dyn smem.
// ---------------------------------------------------------------------------
#define BK_APAR 0                       // Apar[2][128][40] halves
#define BK_BE   (2 * 128 * 40)          // 10240: Be[32][40]
#define BK_BO   (BK_BE + 32 * 40)       // 11520: Bo[32][40]
#define BK_KTS  (BK_BO + 32 * 40)       // 12800: Kt_s[128][136]
#define BK_SMEM ((BK_KTS + 128 * 136) * 2)  // 60416 bytes

__global__ __launch_bounds__(256) void build_kt_tc(const float* __restrict__ k) {
    extern __shared__ __half dynb[];

    int bx = blockIdx.x;
    int l  = bx & 63;
    int bh = bx >> 6;
    int b  = bh >> 4, h = bh & 15;
    int tid  = threadIdx.x;
    int lane = tid & 31;
    int w    = tid >> 5;

    const float* kbase = k + (size_t)b * BSTRIDE + (size_t)l * ROWSTRIDE + h * DDIM;

    // load K [128n][64d], deinterleave parity -> Apar[p][n][t] fp16 (d = 2t+p)
#pragma unroll
    for (int i = 0; i < 8; i++) {
        int idx = tid + i * 256;
        int n = idx >> 4, dq = idx & 15;
        float4 v = *(const float4*)(kbase + (size_t)n * SEGSTRIDE + dq * 4);
        *(__half2*)&dynb[BK_APAR + n * 40 + 2 * dq]        = __floats2half2_rn(v.x, v.z);
        *(__half2*)&dynb[BK_APAR + 5120 + n * 40 + 2 * dq] = __floats2half2_rn(v.y, v.w);
    }
    // tap matrices: Bo[dd][t] = ct(2dd-2t-1) (even outs from odd ins),
    //               Be[dd][t] = ct(2dd+1-2t) (odd outs from even ins),
    // ct(delta) = -cot(pi*delta/64)/64, delta odd.
#pragma unroll
    for (int i = 0; i < 8; i++) {
        int idx = tid + i * 256;               // 0..2047
        int which = idx >> 10, dd = (idx >> 5) & 31, t = idx & 31;
        int delta = which ? (2 * dd + 1 - 2 * t) : (2 * dd - 2 * t - 1);
        float x = (float)delta * (1.0f / 64.0f);
        float val = -(cospif(x) / sinpif(x)) * (1.0f / 64.0f);
        dynb[(which ? BK_BE : BK_BO) + dd * 40 + t] = __float2half(val);
    }
    __syncthreads();

    uint32_t sb = smem_u32(dynb);
    int n0 = w * 16;
    int g = lane >> 2, t4 = lane & 3;

    float cacc[2][4][4];
#pragma unroll
    for (int P = 0; P < 2; P++)
#pragma unroll
        for (int j8 = 0; j8 < 4; j8++)
#pragma unroll
            for (int r = 0; r < 4; r++) cacc[P][j8][r] = 0.0f;

    // im GEMMs: P=0 (even outs): A=Apar[1](odd ins), B=Bo; P=1: A=Apar[0], B=Be.
#pragma unroll
    for (int P = 0; P < 2; P++) {
        uint32_t Abase = sb + (uint32_t)(BK_APAR + (1 - P) * 5120) * 2;
        uint32_t Bbase = sb + (uint32_t)(P ? BK_BE : BK_BO) * 2;
#pragma unroll
        for (int s = 0; s < 2; s++) {
            unsigned a[4];
            uint32_t arow = n0 + (lane & 7) + ((lane >> 3) & 1) * 8;
            uint32_t acol = ((lane >> 4) & 1) * 8 + s * 16;
            ldsm_x4(a, Abase + (arow * 40 + acol) * 2);
#pragma unroll
            for (int dt = 0; dt < 2; dt++) {
                unsigned bb[4];
                uint32_t brow = dt * 16 + (lane & 7) + ((lane >> 4) & 1) * 8;
                uint32_t bcol = ((lane >> 3) & 1) * 8 + s * 16;
                ldsm_x4(bb, Bbase + (brow * 40 + bcol) * 2);
                mma_f16(cacc[P][dt * 2 + 0], a, bb[0], bb[1]);
                mma_f16(cacc[P][dt * 2 + 1], a, bb[2], bb[3]);
            }
        }
    }

    // re part: threads 0..127, one n-row each
    if (tid < 128) {
        int n = tid;
        float ke[32], ko[32];
        float se = 0.0f, so = 0.0f;
#pragma unroll
        for (int t = 0; t < 32; t++) {
            ke[t] = __half2float(dynb[BK_APAR + n * 40 + t]);
            ko[t] = __half2float(dynb[BK_APAR + 5120 + n * 40 + t]);
            se += ke[t];
            so += ko[t];
        }
        se *= (1.0f / 64.0f);
        so *= (1.0f / 64.0f);
#pragma unroll
        for (int t = 0; t < 32; t++) {
            *(__half2*)&dynb[BK_KTS + n * 136 + 2 * t] =
                __floats2half2_rn(0.5f * ke[t] + se, 0.5f * ko[t] + so);
        }
    }

    // im epilogue: d = P + 2*dout, col = 64 + d
#pragma unroll
    for (int P = 0; P < 2; P++) {
#pragma unroll
        for (int j8 = 0; j8 < 4; j8++) {
            int db = j8 * 8;
            int col0 = 64 + P + 2 * (db + 2 * t4);
            int row = n0 + g;
            dynb[BK_KTS + row * 136 + col0]           = __float2half(cacc[P][j8][0]);
            dynb[BK_KTS + row * 136 + col0 + 2]       = __float2half(cacc[P][j8][1]);
            dynb[BK_KTS + (row + 8) * 136 + col0]     = __float2half(cacc[P][j8][2]);
            dynb[BK_KTS + (row + 8) * 136 + col0 + 2] = __float2half(cacc[P][j8][3]);
        }
    }
    __syncthreads();

    // coalesced copy out
    __half* gout = g_KtF + ((size_t)bh * 64 + l) * (128 * 128);
#pragma unroll
    for (int i = 0; i < 8; i++) {
        int idx = tid + i * 256;
        int n = idx >> 4, c = idx & 15;
        *(uint4*)(gout + (size_t)n * 128 + c * 8) = *(uint4*)&dynb[BK_KTS + n * 136 + c * 8];
    }
}

// ---------------------------------------------------------------------------
// Kernel 2: scores GEMM, FP16 mma + ldmatrix, double-buffered, 1 sync/tile.
// B tile = raw copies of Kt (re rows 0:128, im rows 128:256).
// grid (KCH=2, bh=64), block 512, tile 128m x 256j, ktile 32.
// ---------------------------------------------------------------------------
#define A_HALVES (128 * 40)
#define BUF_HALVES (A_HALVES + 256 * 40)
#define SC_SMEM (2 * BUF_HALVES * 2)

__global__ __launch_bounds__(512, 1) void gemm_scores_h4(const float* __restrict__ q) {
    extern __shared__ __half dynh[];

    int kc = blockIdx.x;
    int bh = blockIdx.y;
    int b  = bh >> 4, h = bh & 15;
    int tid  = threadIdx.x;
    int lane = tid & 31;
    int w    = tid >> 5;
    int g = lane >> 2, t = lane & 3;
    int m0 = (w >> 2) * 32;
    int j0 = (w & 3) * 64;

    float dacc[2][8][4];
#pragma unroll
    for (int mi = 0; mi < 2; mi++)
#pragma unroll
        for (int nj = 0; nj < 8; nj++)
#pragma unroll
            for (int r = 0; r < 4; r++) dacc[mi][nj][r] = 0.0f;

    const float*  qb  = q + (size_t)b * BSTRIDE + h * DDIM;
    const __half* ktb = g_KtF + (size_t)bh * (64 * 128 * 128);

    int mI  = tid >> 2;
    int k8I = (tid & 3) * 8;

    uint32_t sbase = smem_u32(dynh);
    uint32_t offA[2], offB[4];
#pragma unroll
    for (int mi = 0; mi < 2; mi++) {
        int row = m0 + mi * 16 + (lane & 7) + ((lane >> 3) & 1) * 8;
        int col = ((lane >> 4) & 1) * 8;
        offA[mi] = (uint32_t)(row * 40 + col) * 2;
    }
#pragma unroll
    for (int njp = 0; njp < 4; njp++) {
        int row = j0 + njp * 16 + (lane & 7) + ((lane >> 4) & 1) * 8;
        int col = ((lane >> 3) & 1) * 8;
        offB[njp] = (uint32_t)(A_HALVES + row * 40 + col) * 2;
    }
    uint32_t stsA  = (uint32_t)(mI * 40 + k8I);
    uint32_t stsBr = (uint32_t)(A_HALVES + mI * 40 + k8I);
    uint32_t stsBi = (uint32_t)(A_HALVES + (128 + mI) * 40 + k8I);

    float4 ar0, ar1;
    uint4  bre, bim;

    // prologue: tile kt=0
    {
        int l = kc * 32;
        const float* sq = qb + (size_t)(mI * LSEG + l) * ROWSTRIDE + k8I;
        ar0 = *(const float4*)sq;
        ar1 = *(const float4*)(sq + 4);
        const __half* sk = ktb + ((size_t)l * 128 + mI) * 128 + k8I;
        bre = *(const uint4*)sk;
        bim = *(const uint4*)(sk + 64);
    }

    for (int kt = 0; kt < 64; kt++) {
        int buf = kt & 1;
        __half* bp = dynh + buf * BUF_HALVES;
        {
            uint4 u;
            u.x = h2u(ar0.x, ar0.y);
            u.y = h2u(ar0.z, ar0.w);
            u.z = h2u(ar1.x, ar1.y);
            u.w = h2u(ar1.z, ar1.w);
            *(uint4*)(bp + stsA)  = u;
            *(uint4*)(bp + stsBr) = bre;
            *(uint4*)(bp + stsBi) = bim;
        }
        if (kt + 1 < 64) {
            int kap = kc * 2048 + (kt + 1) * 32;
            int l   = kap >> 6;
            int dst = kap & 63;
            const float* sq = qb + (size_t)(mI * LSEG + l) * ROWSTRIDE + dst + k8I;
            ar0 = *(const float4*)sq;
            ar1 = *(const float4*)(sq + 4);
            const __half* sk = ktb + ((size_t)l * 128 + mI) * 128 + dst + k8I;
            bre = *(const uint4*)sk;
            bim = *(const uint4*)(sk + 64);
        }
        __syncthreads();

        uint32_t bb0 = sbase + buf * (BUF_HALVES * 2);
#pragma unroll
        for (int s = 0; s < 2; s++) {
            uint32_t so = bb0 + s * 32;
            unsigned a[2][4];
#pragma unroll
            for (int mi = 0; mi < 2; mi++) ldsm_x4(a[mi], so + offA[mi]);
#pragma unroll
            for (int njp = 0; njp < 4; njp++) {
                unsigned bbv[4];
                ldsm_x4(bbv, so + offB[njp]);
#pragma unroll
                for (int mi = 0; mi < 2; mi++) {
                    mma_f16(dacc[mi][2 * njp],     a[mi], bbv[0], bbv[1]);
                    mma_f16(dacc[mi][2 * njp + 1], a[mi], bbv[2], bbv[3]);
                }
            }
        }
    }

    float* cp = g_Cpart + ((size_t)(kc * BH + bh) * MSEG) * 256;
#pragma unroll
    for (int mi = 0; mi < 2; mi++) {
#pragma unroll
        for (int nj = 0; nj < 8; nj++) {
            int r = m0 + mi * 16 + g;
            int c = j0 + nj * 8 + 2 * t;
            *(float2*)(cp + (size_t)r * 256 + c)       = make_float2(dacc[mi][nj][0], dacc[mi][nj][1]);
            *(float2*)(cp + (size_t)(r + 8) * 256 + c) = make_float2(dacc[mi][nj][2], dacc[mi][nj][3]);
        }
    }
}

// ---------------------------------------------------------------------------
// Kernel 3: reduce partials, |S|/512, row softmax -> g_Ah (fp16)
// ---------------------------------------------------------------------------
__global__ __launch_bounds__(256) void softmax_k() {
    int bh   = blockIdx.x;
    int m    = blockIdx.y * 8 + (threadIdx.x >> 5);
    int lane = threadIdx.x & 31;

    float t[4];
#pragma unroll
    for (int u = 0; u < 4; u++) {
        int n = lane + u * 32;
        float sre = 0.0f, sim = 0.0f;
#pragma unroll
        for (int p = 0; p < KCH; p++) {
            const float* cp = g_Cpart + (((size_t)p * BH + bh) * MSEG + m) * 256;
            sre += cp[n];
            sim += cp[n + 128];
        }
        t[u] = sqrtf(sre * sre + sim * sim) * (1.0f / 512.0f);
    }
    float mx = fmaxf(fmaxf(t[0], t[1]), fmaxf(t[2], t[3]));
#pragma unroll
    for (int o = 16; o; o >>= 1) mx = fmaxf(mx, __shfl_xor_sync(0xffffffffu, mx, o));
    float e[4], s = 0.0f;
#pragma unroll
    for (int u = 0; u < 4; u++) { e[u] = expf(t[u] - mx); s += e[u]; }
#pragma unroll
    for (int o = 16; o; o >>= 1) s += __shfl_xor_sync(0xffffffffu, s, o);
    float inv = 1.0f / s;
    __half* arow = g_Ah + ((size_t)bh * MSEG + m) * MSEG;
#pragma unroll
    for (int u = 0; u < 4; u++) arow[lane + u * 32] = __float2half(e[u] * inv);
}

// ---------------------------------------------------------------------------
// Kernel 4: out = A @ v, FP16 mma. A resident, 8 l per CTA, v double-buffered,
// single sync per l. grid (bh*8), block 256.
// ---------------------------------------------------------------------------
__global__ __launch_bounds__(256, 2) void v_gemm_h3(const float* __restrict__ v,
                                                    float* __restrict__ out) {
    extern __shared__ char dynsm[];
    __half (*As)[136]  = (__half(*)[136])dynsm;
    __half2 (*vsp)[72] = (__half2(*)[72])(dynsm + 128 * 136 * 2);

    int bx = blockIdx.x;
    int lg = bx & 7;
    int bh = bx >> 3;
    int b  = bh >> 4, h = bh & 15;
    int tid  = threadIdx.x;
    int lane = tid & 31;
    int w    = tid >> 5;
    int g = lane >> 2, t = lane & 3;
    int m0 = (w >> 1) * 32;
    int d0 = (w & 1) * 32;

    const __half* Abase = g_Ah + (size_t)bh * MSEG * MSEG;
    const float* vbh    = v + (size_t)b * BSTRIDE + h * DDIM;
    float* obh          = out + (size_t)b * BSTRIDE + h * DDIM;

    int kpV = tid >> 4;
    int d4V = tid & 15;

    float4 pv[8];
    {
        const float* vb = vbh + (size_t)(lg * LPB) * ROWSTRIDE;
#pragma unroll
        for (int i = 0; i < 4; i++) {
            int kp = kpV + 16 * i;
            pv[2 * i]     = *(const float4*)(vb + (size_t)(2 * kp) * SEGSTRIDE + d4V * 4);
            pv[2 * i + 1] = *(const float4*)(vb + (size_t)(2 * kp + 1) * SEGSTRIDE + d4V * 4);
        }
    }

#pragma unroll
    for (int i = 0; i < 8; i++) {
        int idx = tid + i * 256;
        int m = idx >> 4, c = idx & 15;
        uint4 u = *(const uint4*)(Abase + (size_t)m * MSEG + c * 8);
        *(uint4*)&As[m][c * 8] = u;
    }

    for (int il = 0; il < LPB; il++) {
        int l   = lg * LPB + il;
        int buf = (il & 1) * 64;
#pragma unroll
        for (int i = 0; i < 4; i++) {
            int kp = kpV + 16 * i;
            uint4 u;
            u.x = h2u(pv[2 * i].x, pv[2 * i + 1].x);
            u.y = h2u(pv[2 * i].y, pv[2 * i + 1].y);
            u.z = h2u(pv[2 * i].z, pv[2 * i + 1].z);
            u.w = h2u(pv[2 * i].w, pv[2 * i + 1].w);
            *(uint4*)&vsp[buf + kp][d4V * 4] = u;
        }
        if (il + 1 < LPB) {
            const float* vb = vbh + (size_t)(l + 1) * ROWSTRIDE;
#pragma unroll
            for (int i = 0; i < 4; i++) {
                int kp = kpV + 16 * i;
                pv[2 * i]     = *(const float4*)(vb + (size_t)(2 * kp) * SEGSTRIDE + d4V * 4);
                pv[2 * i + 1] = *(const float4*)(vb + (size_t)(2 * kp + 1) * SEGSTRIDE + d4V * 4);
            }
        }
        __syncthreads();

        float dacc[2][4][4];
#pragma unroll
        for (int mi = 0; mi < 2; mi++)
#pragma unroll
            for (int dj = 0; dj < 4; dj++)
#pragma unroll
                for (int r = 0; r < 4; r++) dacc[mi][dj][r] = 0.0f;

#pragma unroll
        for (int s = 0; s < 8; s++) {
            int kb16 = s * 16;
            unsigned bb[4][2];
#pragma unroll
            for (int dj = 0; dj < 4; dj++) {
                int c = d0 + dj * 8 + g;
                bb[dj][0] = *(const unsigned*)&vsp[buf + s * 8 + t][c];
                bb[dj][1] = *(const unsigned*)&vsp[buf + s * 8 + t + 4][c];
            }
#pragma unroll
            for (int mi = 0; mi < 2; mi++) {
                int r = m0 + mi * 16 + g;
                unsigned a[4];
                a[0] = *(const unsigned*)&As[r][kb16 + 2 * t];
                a[1] = *(const unsigned*)&As[r + 8][kb16 + 2 * t];
                a[2] = *(const unsigned*)&As[r][kb16 + 2 * t + 8];
                a[3] = *(const unsigned*)&As[r + 8][kb16 + 2 * t + 8];
#pragma unroll
                for (int dj = 0; dj < 4; dj++) mma_f16(dacc[mi][dj], a, bb[dj][0], bb[dj][1]);
            }
        }

        float* obase = obh + (size_t)l * ROWSTRIDE;
#pragma unroll
        for (int mi = 0; mi < 2; mi++) {
#pragma unroll
            for (int dj = 0; dj < 4; dj++) {
                int r = m0 + mi * 16 + g;
                int c = d0 + dj * 8 + 2 * t;
                *(float2*)(obase + (size_t)r * SEGSTRIDE + c)       = make_float2(dacc[mi][dj][0], dacc[mi][dj][1]);
                *(float2*)(obase + (size_t)(r + 8) * SEGSTRIDE + c) = make_float2(dacc[mi][dj][2], dacc[mi][dj][3]);
            }
        }
    }
}

#define VG_SMEM (128 * 136 * 2 + 2 * 64 * 72 * 4)

// ---------------------------------------------------------------------------
extern "C" void kernel_launch(void* const* d_in, const int* in_sizes, int n_in,
                              void* d_out, int out_size) {
    const float* q = (const float*)d_in[0];
    const float* k = (const float*)d_in[1];
    const float* v = (const float*)d_in[2];
    float* out = (float*)d_out;

    cudaFuncSetAttribute(build_kt_tc, cudaFuncAttributeMaxDynamicSharedMemorySize, BK_SMEM);
    cudaFuncSetAttribute(gemm_scores_h4, cudaFuncAttributeMaxDynamicSharedMemorySize, SC_SMEM);
    cudaFuncSetAttribute(v_gemm_h3, cudaFuncAttributeMaxDynamicSharedMemorySize, VG_SMEM);

    build_kt_tc<<<BH * LSEG, 256, BK_SMEM>>>(k);
    gemm_scores_h4<<<dim3(KCH, BH), 512, SC_SMEM>>>(q);
    softmax_k<<<dim3(BH, 16), 256>>>();
    v_gemm_h3<<<BH * LPB, 256, VG_SMEM>>>(v, out);
}

// round 10
// speedup vs baseline: 4.3329x; 1.1172x over previous
#include <cuda_runtime.h>
#include <cuda_fp16.h>
#include <math.h>
#include <stdint.h>

// FourierAttention R10: build fused into scores (K transform on the fly, in-smem,
// tensor-core im-transform). Kernels: scores_fused, softmax, v_gemm.
// B=4, L=8192, H=16, D=64, Ls=64, M=128.

#define BDIM 4
#define LDIM 8192
#define HDIM 16
#define DDIM 64
#define LSEG 64
#define MSEG 128
#define BH   64
#define KDIM 4096
#define KCH  2
#define LPB  8
#define ROWSTRIDE 1024
#define SEGSTRIDE 65536
#define BSTRIDE (LDIM*ROWSTRIDE)

// Scratch (device globals: allocation-free, graph-capture safe)
__device__ float g_Cpart[(size_t)KCH * BH * MSEG * 256]; // score partials
__device__ __half g_Ah[(size_t)BH * MSEG * MSEG];        // softmax result (fp16)

__device__ __forceinline__ void mma_f16(float* d, const unsigned* a,
                                        unsigned b0, unsigned b1) {
    asm volatile(
        "mma.sync.aligned.m16n8k16.row.col.f32.f16.f16.f32 "
        "{%0,%1,%2,%3},{%4,%5,%6,%7},{%8,%9},{%0,%1,%2,%3};"
        : "+f"(d[0]), "+f"(d[1]), "+f"(d[2]), "+f"(d[3])
        : "r"(a[0]), "r"(a[1]), "r"(a[2]), "r"(a[3]), "r"(b0), "r"(b1));
}

__device__ __forceinline__ unsigned h2u(float a, float b) {
    __half2 h = __floats2half2_rn(a, b);
    return *(unsigned*)&h;
}

__device__ __forceinline__ uint32_t smem_u32(const void* p) {
    uint32_t a;
    asm("{ .reg .u64 t; cvta.to.shared.u64 t, %1; cvt.u32.u64 %0, t; }" : "=r"(a) : "l"(p));
    return a;
}

__device__ __forceinline__ void ldsm_x4(unsigned* r, uint32_t addr) {
    asm volatile("ldmatrix.sync.aligned.m8n8.x4.shared.b16 {%0,%1,%2,%3}, [%4];"
        : "=r"(r[0]), "=r"(r[1]), "=r"(r[2]), "=r"(r[3]) : "r"(addr));
}

// ---------------------------------------------------------------------------
// Kernel 1: fused transform + scores GEMM.
// grid (kc=2, bh=64), block 512 (16 warps), block tile 128m x 256j, 32 l iters.
// Per l: Bs rows 0:128 = re (0.5*K + paritysum/64, computed via shfl),
//        rows 128:256 = im (tensor-core cot-tap GEMM from Apar).
// ---------------------------------------------------------------------------
#define FS_AS 0
#define FS_BS (128 * 72)                // 9216
#define FS_AP (FS_BS + 256 * 72)        // 27648
#define FS_TP (FS_AP + 2 * 128 * 40)    // 37888
#define FS_TOT (FS_TP + 2 * 32 * 40)    // 40448 halves
#define FS_SMEM (FS_TOT * 2)            // 80896 bytes

__global__ __launch_bounds__(512, 1) void scores_fused(const float* __restrict__ q,
                                                       const float* __restrict__ kin) {
    extern __shared__ __half sh[];

    int kc = blockIdx.x;
    int bh = blockIdx.y;
    int b  = bh >> 4, h = bh & 15;
    int tid  = threadIdx.x;
    int lane = tid & 31;
    int w    = tid >> 5;
    int g = lane >> 2, t4 = lane & 3;
    int m0 = (w >> 2) * 32;
    int j0 = (w & 3) * 64;

    // cot tap matrices: taps[0]=Bo (even outs), taps[1]=Be (odd outs)
#pragma unroll
    for (int i = tid; i < 2048; i += 512) {
        int which = i >> 10, dd = (i >> 5) & 31, tt = i & 31;
        int delta = which ? (2 * dd + 1 - 2 * tt) : (2 * dd - 2 * tt - 1);
        float x = (float)delta * (1.0f / 64.0f);
        float val = -(cospif(x) / sinpif(x)) * (1.0f / 64.0f);
        sh[FS_TP + which * (32 * 40) + dd * 40 + tt] = __float2half(val);
    }

    float dacc[2][8][4];
#pragma unroll
    for (int mi = 0; mi < 2; mi++)
#pragma unroll
        for (int nj = 0; nj < 8; nj++)
#pragma unroll
            for (int r = 0; r < 4; r++) dacc[mi][nj][r] = 0.0f;

    const float* qb = q   + (size_t)b * BSTRIDE + h * DDIM;
    const float* kb = kin + (size_t)b * BSTRIDE + h * DDIM;

    int n   = tid >> 2;
    int q16 = (tid & 3) * 16;
    int q8  = (tid & 3) * 8;

    uint32_t sb = smem_u32(sh);
    // main-MMA ldmatrix offsets
    uint32_t offA[2], offB[4];
#pragma unroll
    for (int mi = 0; mi < 2; mi++) {
        int row = m0 + mi * 16 + (lane & 7) + ((lane >> 3) & 1) * 8;
        int col = ((lane >> 4) & 1) * 8;
        offA[mi] = sb + (uint32_t)(FS_AS + row * 72 + col) * 2;
    }
#pragma unroll
    for (int njp = 0; njp < 4; njp++) {
        int row = j0 + njp * 16 + (lane & 7) + ((lane >> 4) & 1) * 8;
        int col = ((lane >> 3) & 1) * 8;
        offB[njp] = sb + (uint32_t)(FS_BS + row * 72 + col) * 2;
    }
    // transform assignment: warp w -> parity P, 16 n-rows
    int P    = w & 1;
    int nblk = (w >> 1) * 16;
    uint32_t offTA, offTB[2];
    {
        int row = nblk + (lane & 7) + ((lane >> 3) & 1) * 8;
        int col = ((lane >> 4) & 1) * 8;
        offTA = sb + (uint32_t)(FS_AP + (1 - P) * (128 * 40) + row * 40 + col) * 2;
#pragma unroll
        for (int dt = 0; dt < 2; dt++) {
            int br = dt * 16 + (lane & 7) + ((lane >> 4) & 1) * 8;
            int bc = ((lane >> 3) & 1) * 8;
            offTB[dt] = sb + (uint32_t)(FS_TP + P * (32 * 40) + br * 40 + bc) * 2;
        }
    }

    float4 qv[4], kv[4];
    // prologue: load l = kc*32
    {
        const float* sq = qb + (size_t)(n * LSEG + kc * 32) * ROWSTRIDE + q16;
        const float* sk = kb + (size_t)(n * LSEG + kc * 32) * ROWSTRIDE + q16;
#pragma unroll
        for (int i = 0; i < 4; i++) {
            qv[i] = *(const float4*)(sq + i * 4);
            kv[i] = *(const float4*)(sk + i * 4);
        }
    }

    for (int il = 0; il < 32; il++) {
        __syncthreads();   // (a) prev main-MMA done (il=0: taps written)

        // ---- STS phase ----
        {
            uint4 ua, ub;
            ua.x = h2u(qv[0].x, qv[0].y); ua.y = h2u(qv[0].z, qv[0].w);
            ua.z = h2u(qv[1].x, qv[1].y); ua.w = h2u(qv[1].z, qv[1].w);
            ub.x = h2u(qv[2].x, qv[2].y); ub.y = h2u(qv[2].z, qv[2].w);
            ub.z = h2u(qv[3].x, qv[3].y); ub.w = h2u(qv[3].z, qv[3].w);
            *(uint4*)&sh[FS_AS + n * 72 + q16]     = ua;
            *(uint4*)&sh[FS_AS + n * 72 + q16 + 8] = ub;

            float e0 = kv[0].x, e1 = kv[0].z, e2 = kv[1].x, e3 = kv[1].z;
            float e4 = kv[2].x, e5 = kv[2].z, e6 = kv[3].x, e7 = kv[3].z;
            float o0 = kv[0].y, o1 = kv[0].w, o2 = kv[1].y, o3 = kv[1].w;
            float o4 = kv[2].y, o5 = kv[2].w, o6 = kv[3].y, o7 = kv[3].w;
            float se = ((e0 + e1) + (e2 + e3)) + ((e4 + e5) + (e6 + e7));
            float so = ((o0 + o1) + (o2 + o3)) + ((o4 + o5) + (o6 + o7));
            se += __shfl_xor_sync(0xffffffffu, se, 1);
            se += __shfl_xor_sync(0xffffffffu, se, 2);
            so += __shfl_xor_sync(0xffffffffu, so, 1);
            so += __shfl_xor_sync(0xffffffffu, so, 2);
            se *= (1.0f / 64.0f);
            so *= (1.0f / 64.0f);

            // re rows of Bs
            uint4 ra, rb;
            ra.x = h2u(0.5f * e0 + se, 0.5f * o0 + so);
            ra.y = h2u(0.5f * e1 + se, 0.5f * o1 + so);
            ra.z = h2u(0.5f * e2 + se, 0.5f * o2 + so);
            ra.w = h2u(0.5f * e3 + se, 0.5f * o3 + so);
            rb.x = h2u(0.5f * e4 + se, 0.5f * o4 + so);
            rb.y = h2u(0.5f * e5 + se, 0.5f * o5 + so);
            rb.z = h2u(0.5f * e6 + se, 0.5f * o6 + so);
            rb.w = h2u(0.5f * e7 + se, 0.5f * o7 + so);
            *(uint4*)&sh[FS_BS + n * 72 + q16]     = ra;
            *(uint4*)&sh[FS_BS + n * 72 + q16 + 8] = rb;

            // Apar (even set then odd set), fp16
            uint4 pe, po;
            pe.x = h2u(e0, e1); pe.y = h2u(e2, e3); pe.z = h2u(e4, e5); pe.w = h2u(e6, e7);
            po.x = h2u(o0, o1); po.y = h2u(o2, o3); po.z = h2u(o4, o5); po.w = h2u(o6, o7);
            *(uint4*)&sh[FS_AP + n * 40 + q8]            = pe;
            *(uint4*)&sh[FS_AP + 128 * 40 + n * 40 + q8] = po;
        }
        __syncthreads();   // (b)

        // ---- transform MMAs (im rows) ----
        float cacc[4][4];
#pragma unroll
        for (int j8 = 0; j8 < 4; j8++)
#pragma unroll
            for (int r = 0; r < 4; r++) cacc[j8][r] = 0.0f;
#pragma unroll
        for (int s = 0; s < 2; s++) {
            unsigned a[4];
            ldsm_x4(a, offTA + s * 32);
#pragma unroll
            for (int dt = 0; dt < 2; dt++) {
                unsigned bbv[4];
                ldsm_x4(bbv, offTB[dt] + s * 32);
                mma_f16(cacc[dt * 2 + 0], a, bbv[0], bbv[1]);
                mma_f16(cacc[dt * 2 + 1], a, bbv[2], bbv[3]);
            }
        }
        // im epilogue: d = P + 2*dout
#pragma unroll
        for (int j8 = 0; j8 < 4; j8++) {
            int col0 = P + 2 * (j8 * 8 + 2 * t4);
            int row  = nblk + g;
            sh[FS_BS + (128 + row) * 72 + col0]           = __float2half(cacc[j8][0]);
            sh[FS_BS + (128 + row) * 72 + col0 + 2]       = __float2half(cacc[j8][1]);
            sh[FS_BS + (128 + row + 8) * 72 + col0]       = __float2half(cacc[j8][2]);
            sh[FS_BS + (128 + row + 8) * 72 + col0 + 2]   = __float2half(cacc[j8][3]);
        }

        // prefetch next l (regs free after STS)
        if (il + 1 < 32) {
            int l2 = kc * 32 + il + 1;
            const float* sq = qb + (size_t)(n * LSEG + l2) * ROWSTRIDE + q16;
            const float* sk = kb + (size_t)(n * LSEG + l2) * ROWSTRIDE + q16;
#pragma unroll
            for (int i = 0; i < 4; i++) {
                qv[i] = *(const float4*)(sq + i * 4);
                kv[i] = *(const float4*)(sk + i * 4);
            }
        }
        __syncthreads();   // (c)

        // ---- main MMA: 4 k16 steps over 64 k-cols ----
#pragma unroll
        for (int s = 0; s < 4; s++) {
            uint32_t so = s * 32;   // 16 halves
            unsigned a[2][4];
#pragma unroll
            for (int mi = 0; mi < 2; mi++) ldsm_x4(a[mi], offA[mi] + so);
#pragma unroll
            for (int njp = 0; njp < 4; njp++) {
                unsigned bbv[4];
                ldsm_x4(bbv, offB[njp] + so);
#pragma unroll
                for (int mi = 0; mi < 2; mi++) {
                    mma_f16(dacc[mi][2 * njp],     a[mi], bbv[0], bbv[1]);
                    mma_f16(dacc[mi][2 * njp + 1], a[mi], bbv[2], bbv[3]);
                }
            }
        }
    }

    float* cp = g_Cpart + ((size_t)(kc * BH + bh) * MSEG) * 256;
#pragma unroll
    for (int mi = 0; mi < 2; mi++) {
#pragma unroll
        for (int nj = 0; nj < 8; nj++) {
            int r = m0 + mi * 16 + g;
            int c = j0 + nj * 8 + 2 * t4;
            *(float2*)(cp + (size_t)r * 256 + c)       = make_float2(dacc[mi][nj][0], dacc[mi][nj][1]);
            *(float2*)(cp + (size_t)(r + 8) * 256 + c) = make_float2(dacc[mi][nj][2], dacc[mi][nj][3]);
        }
    }
}

// ---------------------------------------------------------------------------
// Kernel 2: reduce partials, |S|/512, row softmax -> g_Ah (fp16)
// ---------------------------------------------------------------------------
__global__ __launch_bounds__(256) void softmax_k() {
    int bh   = blockIdx.x;
    int m    = blockIdx.y * 8 + (threadIdx.x >> 5);
    int lane = threadIdx.x & 31;

    float t[4];
#pragma unroll
    for (int u = 0; u < 4; u++) {
        int n = lane + u * 32;
        float sre = 0.0f, sim = 0.0f;
#pragma unroll
        for (int p = 0; p < KCH; p++) {
            const float* cp = g_Cpart + (((size_t)p * BH + bh) * MSEG + m) * 256;
            sre += cp[n];
            sim += cp[n + 128];
        }
        t[u] = sqrtf(sre * sre + sim * sim) * (1.0f / 512.0f);
    }
    float mx = fmaxf(fmaxf(t[0], t[1]), fmaxf(t[2], t[3]));
#pragma unroll
    for (int o = 16; o; o >>= 1) mx = fmaxf(mx, __shfl_xor_sync(0xffffffffu, mx, o));
    float e[4], s = 0.0f;
#pragma unroll
    for (int u = 0; u < 4; u++) { e[u] = expf(t[u] - mx); s += e[u]; }
#pragma unroll
    for (int o = 16; o; o >>= 1) s += __shfl_xor_sync(0xffffffffu, s, o);
    float inv = 1.0f / s;
    __half* arow = g_Ah + ((size_t)bh * MSEG + m) * MSEG;
#pragma unroll
    for (int u = 0; u < 4; u++) arow[lane + u * 32] = __float2half(e[u] * inv);
}

// ---------------------------------------------------------------------------
// Kernel 3: out = A @ v, FP16 mma. A resident, 8 l per CTA, v double-buffered,
// single sync per l. grid (bh*8), block 256.  (unchanged from R9)
// ---------------------------------------------------------------------------
__global__ __launch_bounds__(256, 2) void v_gemm_h3(const float* __restrict__ v,
                                                    float* __restrict__ out) {
    extern __shared__ char dynsm[];
    __half (*As)[136]  = (__half(*)[136])dynsm;
    __half2 (*vsp)[72] = (__half2(*)[72])(dynsm + 128 * 136 * 2);

    int bx = blockIdx.x;
    int lg = bx & 7;
    int bh = bx >> 3;
    int b  = bh >> 4, h = bh & 15;
    int tid  = threadIdx.x;
    int lane = tid & 31;
    int w    = tid >> 5;
    int g = lane >> 2, t = lane & 3;
    int m0 = (w >> 1) * 32;
    int d0 = (w & 1) * 32;

    const __half* Abase = g_Ah + (size_t)bh * MSEG * MSEG;
    const float* vbh    = v + (size_t)b * BSTRIDE + h * DDIM;
    float* obh          = out + (size_t)b * BSTRIDE + h * DDIM;

    int kpV = tid >> 4;
    int d4V = tid & 15;

    float4 pv[8];
    {
        const float* vb = vbh + (size_t)(lg * LPB) * ROWSTRIDE;
#pragma unroll
        for (int i = 0; i < 4; i++) {
            int kp = kpV + 16 * i;
            pv[2 * i]     = *(const float4*)(vb + (size_t)(2 * kp) * SEGSTRIDE + d4V * 4);
            pv[2 * i + 1] = *(const float4*)(vb + (size_t)(2 * kp + 1) * SEGSTRIDE + d4V * 4);
        }
    }

#pragma unroll
    for (int i = 0; i < 8; i++) {
        int idx = tid + i * 256;
        int m = idx >> 4, c = idx & 15;
        uint4 u = *(const uint4*)(Abase + (size_t)m * MSEG + c * 8);
        *(uint4*)&As[m][c * 8] = u;
    }

    for (int il = 0; il < LPB; il++) {
        int l   = lg * LPB + il;
        int buf = (il & 1) * 64;
#pragma unroll
        for (int i = 0; i < 4; i++) {
            int kp = kpV + 16 * i;
            uint4 u;
            u.x = h2u(pv[2 * i].x, pv[2 * i + 1].x);
            u.y = h2u(pv[2 * i].y, pv[2 * i + 1].y);
            u.z = h2u(pv[2 * i].z, pv[2 * i + 1].z);
            u.w = h2u(pv[2 * i].w, pv[2 * i + 1].w);
            *(uint4*)&vsp[buf + kp][d4V * 4] = u;
        }
        if (il + 1 < LPB) {
            const float* vb = vbh + (size_t)(l + 1) * ROWSTRIDE;
#pragma unroll
            for (int i = 0; i < 4; i++) {
                int kp = kpV + 16 * i;
                pv[2 * i]     = *(const float4*)(vb + (size_t)(2 * kp) * SEGSTRIDE + d4V * 4);
                pv[2 * i + 1] = *(const float4*)(vb + (size_t)(2 * kp + 1) * SEGSTRIDE + d4V * 4);
            }
        }
        __syncthreads();

        float dacc[2][4][4];
#pragma unroll
        for (int mi = 0; mi < 2; mi++)
#pragma unroll
            for (int dj = 0; dj < 4; dj++)
#pragma unroll
                for (int r = 0; r < 4; r++) dacc[mi][dj][r] = 0.0f;

#pragma unroll
        for (int s = 0; s < 8; s++) {
            int kb16 = s * 16;
            unsigned bb[4][2];
#pragma unroll
            for (int dj = 0; dj < 4; dj++) {
                int c = d0 + dj * 8 + g;
                bb[dj][0] = *(const unsigned*)&vsp[buf + s * 8 + t][c];
                bb[dj][1] = *(const unsigned*)&vsp[buf + s * 8 + t + 4][c];
            }
#pragma unroll
            for (int mi = 0; mi < 2; mi++) {
                int r = m0 + mi * 16 + g;
                unsigned a[4];
                a[0] = *(const unsigned*)&As[r][kb16 + 2 * t];
                a[1] = *(const unsigned*)&As[r + 8][kb16 + 2 * t];
                a[2] = *(const unsigned*)&As[r][kb16 + 2 * t + 8];
                a[3] = *(const unsigned*)&As[r + 8][kb16 + 2 * t + 8];
#pragma unroll
                for (int dj = 0; dj < 4; dj++) mma_f16(dacc[mi][dj], a, bb[dj][0], bb[dj][1]);
            }
        }

        float* obase = obh + (size_t)l * ROWSTRIDE;
#pragma unroll
        for (int mi = 0; mi < 2; mi++) {
#pragma unroll
            for (int dj = 0; dj < 4; dj++) {
                int r = m0 + mi * 16 + g;
                int c = d0 + dj * 8 + 2 * t;
                *(float2*)(obase + (size_t)r * SEGSTRIDE + c)       = make_float2(dacc[mi][dj][0], dacc[mi][dj][1]);
                *(float2*)(obase + (size_t)(r + 8) * SEGSTRIDE + c) = make_float2(dacc[mi][dj][2], dacc[mi][dj][3]);
            }
        }
    }
}

#define VG_SMEM (128 * 136 * 2 + 2 * 64 * 72 * 4)

// ---------------------------------------------------------------------------
extern "C" void kernel_launch(void* const* d_in, const int* in_sizes, int n_in,
                              void* d_out, int out_size) {
    const float* q = (const float*)d_in[0];
    const float* k = (const float*)d_in[1];
    const float* v = (const float*)d_in[2];
    float* out = (float*)d_out;

    cudaFuncSetAttribute(scores_fused, cudaFuncAttributeMaxDynamicSharedMemorySize, FS_SMEM);
    cudaFuncSetAttribute(v_gemm_h3, cudaFuncAttributeMaxDynamicSharedMemorySize, VG_SMEM);

    scores_fused<<<dim3(KCH, BH), 512, FS_SMEM>>>(q, k);
    softmax_k<<<dim3(BH, 16), 256>>>();
    v_gemm_h3<<<BH * LPB, 256, VG_SMEM>>>(v, out);
}